// round 1
// baseline (speedup 1.0000x reference)
#include <cuda_runtime.h>
#include <math.h>

#define B_  32
#define T_  384
#define D_  512
#define H_  16
#define BTD (B_*T_*D_)     // 6291456
#define M_  (B_*T_)        // 12288

// Scratch buffers (no cudaMalloc allowed)
__device__ float g_q[BTD], g_k[BTD], g_v[BTD];
__device__ float g_xr[BTD], g_t1[BTD], g_t2[BTD], g_ln[BTD];
__device__ float g_a1[BTD], g_a2[BTD];

// ---------------------------------------------------------------------------
// GEMM: C(M,N) = A(M,K) @ W(N,K)^T + bias  (all row-major, K=N=512)
// chunkMode=1: weight/bias index = (m0 % 384)/128  (blocks 1..3 on T-chunks)
// Tile 128x64, 256 threads, 8x4 micro-tile, K-step 16.
// ---------------------------------------------------------------------------
__global__ __launch_bounds__(256) void gemm_nt(
    const float* __restrict__ A, const float* __restrict__ W,
    const float* __restrict__ bias, float* __restrict__ C,
    int chunkMode)
{
    const int K = 512, N = 512;
    __shared__ float As[16][128];
    __shared__ float Bs[16][64];
    const int m0 = blockIdx.y * 128;
    const int n0 = blockIdx.x * 64;
    const int widx = chunkMode ? ((m0 % 384) / 128) : 0;
    const float* Wp = W + (size_t)widx * (N * K);
    const float* bp = bias + widx * N;
    const int tid = threadIdx.x;
    const int ry = tid >> 4;      // 0..15, covers 8 rows each
    const int cx = tid & 15;      // 0..15, covers 4 cols each
    float acc[8][4];
#pragma unroll
    for (int i = 0; i < 8; i++)
#pragma unroll
        for (int j = 0; j < 4; j++) acc[i][j] = 0.f;

    const int bn  = tid >> 2;       // 0..63 (B tile row)
    const int bkq = (tid & 3) * 4;  // k offset

    for (int kt = 0; kt < K; kt += 16) {
#pragma unroll
        for (int r = 0; r < 2; r++) {
            int vv = tid + r * 256;
            int m  = vv >> 2;
            int kq = (vv & 3) * 4;
            float4 a = *(const float4*)(A + (size_t)(m0 + m) * K + kt + kq);
            As[kq+0][m] = a.x; As[kq+1][m] = a.y; As[kq+2][m] = a.z; As[kq+3][m] = a.w;
        }
        {
            float4 b4 = *(const float4*)(Wp + (size_t)(n0 + bn) * K + kt + bkq);
            Bs[bkq+0][bn] = b4.x; Bs[bkq+1][bn] = b4.y; Bs[bkq+2][bn] = b4.z; Bs[bkq+3][bn] = b4.w;
        }
        __syncthreads();
#pragma unroll
        for (int kk = 0; kk < 16; kk++) {
            float av[8], bv[4];
            float4 t0 = *(const float4*)&As[kk][ry*8];
            float4 t1 = *(const float4*)&As[kk][ry*8+4];
            av[0]=t0.x; av[1]=t0.y; av[2]=t0.z; av[3]=t0.w;
            av[4]=t1.x; av[5]=t1.y; av[6]=t1.z; av[7]=t1.w;
            float4 t2 = *(const float4*)&Bs[kk][cx*4];
            bv[0]=t2.x; bv[1]=t2.y; bv[2]=t2.z; bv[3]=t2.w;
#pragma unroll
            for (int i = 0; i < 8; i++)
#pragma unroll
                for (int j = 0; j < 4; j++)
                    acc[i][j] = fmaf(av[i], bv[j], acc[i][j]);
        }
        __syncthreads();
    }
    float4 bb = *(const float4*)(bp + n0 + cx*4);
#pragma unroll
    for (int i = 0; i < 8; i++) {
        int row = m0 + ry*8 + i;
        float4 o;
        o.x = acc[i][0] + bb.x;
        o.y = acc[i][1] + bb.y;
        o.z = acc[i][2] + bb.z;
        o.w = acc[i][3] + bb.w;
        *(float4*)(C + (size_t)row * 512 + n0 + cx*4) = o;
    }
}

// ---------------------------------------------------------------------------
// Fused attention per (b, h [, chunk]) CTA.
// K,V,Q slabs are (32, T) row-major at off = b*T*D + c*128*512 + h*32*T.
// S[t,s] = sum_i K[i,t] V[i,s] * scale;  P = softmax_rows(S);  Out = Q @ P.
// Phase 1 (thread t): online-softmax stats m_t, 1/l_t.
// Phase 2 (thread s): recompute column, accumulate Out[:,s] (+addend).
// blockDim == T (384 or 128).
// ---------------------------------------------------------------------------
__global__ __launch_bounds__(384) void attn_kernel(
    const float* __restrict__ Qb, const float* __restrict__ Kb,
    const float* __restrict__ Vb, const float* __restrict__ temp,
    const float* __restrict__ addend, float* __restrict__ Ob,
    int T, int tempBase)
{
    extern __shared__ float sm[];
    const int h = blockIdx.x, c = blockIdx.y, b = blockIdx.z;
    const int tid = threadIdx.x;
    const int ST = 36;                   // padded row stride (floats)
    float* Kt = sm;                      // [T][36]  Kt[t][i] = K[i,t]
    float* Vt = Kt + T * ST;
    float* Qt = Vt + T * ST;
    float* Mv = Qt + T * ST;             // [T] row max
    float* Lv = Mv + T;                  // [T] 1/row-sum
    const size_t off = (size_t)b * (T_*D_) + (size_t)c * (128*D_) + (size_t)h * 32 * T;
    const float scale = temp[(tempBase + c) * H_ + h];

#pragma unroll
    for (int i = 0; i < 32; i++) {
        Kt[tid*ST + i] = Kb[off + (size_t)i*T + tid];
        Vt[tid*ST + i] = Vb[off + (size_t)i*T + tid];
        Qt[tid*ST + i] = Qb[off + (size_t)i*T + tid];
    }
    __syncthreads();

    float reg[32];
    {   // K[:, t=tid] into registers
        const float4* kr = (const float4*)(Kt + tid*ST);
#pragma unroll
        for (int j = 0; j < 8; j++) {
            float4 f = kr[j];
            reg[4*j]=f.x; reg[4*j+1]=f.y; reg[4*j+2]=f.z; reg[4*j+3]=f.w;
        }
    }
    float m = -3.0e38f, l = 0.f;
    for (int s = 0; s < T; s++) {
        const float4* vr = (const float4*)(Vt + s*ST);   // broadcast reads
        float x = 0.f;
#pragma unroll
        for (int j = 0; j < 8; j++) {
            float4 f = vr[j];
            x = fmaf(reg[4*j],   f.x, x);
            x = fmaf(reg[4*j+1], f.y, x);
            x = fmaf(reg[4*j+2], f.z, x);
            x = fmaf(reg[4*j+3], f.w, x);
        }
        x *= scale;
        if (x <= m) {
            l += __expf(x - m);
        } else {
            l = l * __expf(m - x) + 1.f;
            m = x;
        }
    }
    Mv[tid] = m;
    Lv[tid] = 1.f / l;
    __syncthreads();

    {   // V[:, s=tid] into registers
        const float4* vr = (const float4*)(Vt + tid*ST);
#pragma unroll
        for (int j = 0; j < 8; j++) {
            float4 f = vr[j];
            reg[4*j]=f.x; reg[4*j+1]=f.y; reg[4*j+2]=f.z; reg[4*j+3]=f.w;
        }
    }
    float acc[32];
#pragma unroll
    for (int i = 0; i < 32; i++) acc[i] = 0.f;
    for (int t = 0; t < T; t++) {
        const float4* kr = (const float4*)(Kt + t*ST);   // broadcast
        float x = 0.f;
#pragma unroll
        for (int j = 0; j < 8; j++) {
            float4 f = kr[j];
            x = fmaf(reg[4*j],   f.x, x);
            x = fmaf(reg[4*j+1], f.y, x);
            x = fmaf(reg[4*j+2], f.z, x);
            x = fmaf(reg[4*j+3], f.w, x);
        }
        float p = __expf(fmaf(x, scale, -Mv[t])) * Lv[t];
        const float4* qr = (const float4*)(Qt + t*ST);   // broadcast
#pragma unroll
        for (int j = 0; j < 8; j++) {
            float4 f = qr[j];
            acc[4*j]   = fmaf(p, f.x, acc[4*j]);
            acc[4*j+1] = fmaf(p, f.y, acc[4*j+1]);
            acc[4*j+2] = fmaf(p, f.z, acc[4*j+2]);
            acc[4*j+3] = fmaf(p, f.w, acc[4*j+3]);
        }
    }
    if (addend != nullptr) {
#pragma unroll
        for (int i = 0; i < 32; i++)
            Ob[off + (size_t)i*T + tid] = acc[i] + addend[off + (size_t)i*T + tid];
    } else {
#pragma unroll
        for (int i = 0; i < 32; i++)
            Ob[off + (size_t)i*T + tid] = acc[i];
    }
}

// ---------------------------------------------------------------------------
// LayerNorm: one warp per 512-wide row. 256 threads = 8 rows / CTA.
// ---------------------------------------------------------------------------
__global__ __launch_bounds__(256) void ln_kernel(
    const float* __restrict__ X, const float* __restrict__ gw,
    const float* __restrict__ gb, float* __restrict__ Y)
{
    const int row  = blockIdx.x * 8 + (threadIdx.x >> 5);
    const int lane = threadIdx.x & 31;
    const float4* xr = (const float4*)(X + (size_t)row * D_);
    float4 v[4];
    float s = 0.f, ss = 0.f;
#pragma unroll
    for (int w = 0; w < 4; w++) {
        v[w] = xr[w*32 + lane];
        s  += v[w].x + v[w].y + v[w].z + v[w].w;
        ss += v[w].x*v[w].x + v[w].y*v[w].y + v[w].z*v[w].z + v[w].w*v[w].w;
    }
#pragma unroll
    for (int o = 16; o > 0; o >>= 1) {
        s  += __shfl_xor_sync(0xffffffffu, s, o);
        ss += __shfl_xor_sync(0xffffffffu, ss, o);
    }
    const float mean = s * (1.f/512.f);
    const float var  = ss * (1.f/512.f) - mean*mean;
    const float r = rsqrtf(var + 1e-5f);
    float4* yr = (float4*)(Y + (size_t)row * D_);
    const float4* gr = (const float4*)gw;
    const float4* br = (const float4*)gb;
#pragma unroll
    for (int w = 0; w < 4; w++) {
        float4 gv = gr[w*32 + lane];
        float4 bv = br[w*32 + lane];
        float4 o;
        o.x = (v[w].x - mean) * r * gv.x + bv.x;
        o.y = (v[w].y - mean) * r * gv.y + bv.y;
        o.z = (v[w].z - mean) * r * gv.z + bv.z;
        o.w = (v[w].w - mean) * r * gv.w + bv.w;
        yr[w*32 + lane] = o;
    }
}

// ---------------------------------------------------------------------------
// Fusion gating: out = t1*softmax0 + t2*softmax1 over stacked logits a1,a2
// ---------------------------------------------------------------------------
__device__ __forceinline__ float fuse1(float x1, float x2, float y1, float y2) {
    float mx = fmaxf(y1, y2);
    float e1 = __expf(y1 - mx), e2 = __expf(y2 - mx);
    return (x1*e1 + x2*e2) / (e1 + e2);
}

__global__ __launch_bounds__(256) void fuse_kernel(
    const float4* __restrict__ t1, const float4* __restrict__ t2,
    const float4* __restrict__ a1, const float4* __restrict__ a2,
    float4* __restrict__ out)
{
    int i = blockIdx.x * 256 + threadIdx.x;
    float4 x1 = t1[i], x2 = t2[i], y1 = a1[i], y2 = a2[i];
    float4 o;
    o.x = fuse1(x1.x, x2.x, y1.x, y2.x);
    o.y = fuse1(x1.y, x2.y, y1.y, y2.y);
    o.z = fuse1(x1.z, x2.z, y1.z, y2.z);
    o.w = fuse1(x1.w, x2.w, y1.w, y2.w);
    out[i] = o;
}

// ---------------------------------------------------------------------------
extern "C" void kernel_launch(void* const* d_in, const int* in_sizes, int n_in,
                              void* d_out, int out_size)
{
    (void)in_sizes; (void)n_in; (void)out_size;
    const float* x    = (const float*)d_in[0];
    const float* qw   = (const float*)d_in[1];
    const float* qb   = (const float*)d_in[2];
    const float* kw   = (const float*)d_in[3];
    const float* kb   = (const float*)d_in[4];
    const float* vw   = (const float*)d_in[5];
    const float* vb   = (const float*)d_in[6];
    const float* temp = (const float*)d_in[7];
    const float* lng  = (const float*)d_in[8];
    const float* lnb  = (const float*)d_in[9];
    const float* fw   = (const float*)d_in[10];
    const float* fb   = (const float*)d_in[11];
    float* out = (float*)d_out;

    float *q, *k, *v, *xr, *t1, *t2, *ln, *a1, *a2;
    cudaGetSymbolAddress((void**)&q,  g_q);
    cudaGetSymbolAddress((void**)&k,  g_k);
    cudaGetSymbolAddress((void**)&v,  g_v);
    cudaGetSymbolAddress((void**)&xr, g_xr);
    cudaGetSymbolAddress((void**)&t1, g_t1);
    cudaGetSymbolAddress((void**)&t2, g_t2);
    cudaGetSymbolAddress((void**)&ln, g_ln);
    cudaGetSymbolAddress((void**)&a1, g_a1);
    cudaGetSymbolAddress((void**)&a2, g_a2);

    const int smem384 = (3*384*36 + 2*384) * 4;   // 168960 B
    const int smem128 = (3*128*36 + 2*128) * 4;   // 56320 B
    cudaFuncSetAttribute(attn_kernel, cudaFuncAttributeMaxDynamicSharedMemorySize, smem384);

    const int WKN = 512*512;
    dim3 gg(8, 96);   // N/64, M/128

    // Block 0 (full T) projections + attention -> xr
    gemm_nt<<<gg, 256>>>(x, qw, qb, q, 0);
    gemm_nt<<<gg, 256>>>(x, kw, kb, k, 0);
    gemm_nt<<<gg, 256>>>(x, vw, vb, v, 0);
    attn_kernel<<<dim3(H_,1,B_), 384, smem384>>>(q, k, v, temp, nullptr, xr, 384, 0);

    // Blocks 1-3 (T chunks of 128) in one batched GEMM set + chunked attention
    gemm_nt<<<gg, 256>>>(x, qw + WKN, qb + 512, q, 1);
    gemm_nt<<<gg, 256>>>(x, kw + WKN, kb + 512, k, 1);
    gemm_nt<<<gg, 256>>>(x, vw + WKN, vb + 512, v, 1);
    attn_kernel<<<dim3(H_,3,B_), 128, smem128>>>(q, k, v, temp, xr, t1, 128, 1);

    // LayerNorm(tmp1)
    ln_kernel<<<M_/8, 256>>>(t1, lng, lnb, ln);

    // Block 4 projections + attention -> t2 (+ xr)
    gemm_nt<<<gg, 256>>>(ln, qw + 4*WKN, qb + 4*512, q, 0);
    gemm_nt<<<gg, 256>>>(ln, kw + 4*WKN, kb + 4*512, k, 0);
    gemm_nt<<<gg, 256>>>(ln, vw + 4*WKN, vb + 4*512, v, 0);
    attn_kernel<<<dim3(H_,1,B_), 384, smem384>>>(q, k, v, temp, xr, t2, 384, 4);

    // Fusion gating
    gemm_nt<<<gg, 256>>>(t1, fw, fb, a1, 0);
    gemm_nt<<<gg, 256>>>(t2, fw, fb, a2, 0);
    fuse_kernel<<<BTD/4/256, 256>>>((const float4*)t1, (const float4*)t2,
                                    (const float4*)a1, (const float4*)a2, (float4*)out);
}

// round 2
// speedup vs baseline: 1.6866x; 1.6866x over previous
#include <cuda_runtime.h>
#include <math.h>

#define B_  32
#define T_  384
#define D_  512
#define H_  16
#define BTD (B_*T_*D_)     // 6291456
#define M_  (B_*T_)        // 12288
#define WKN (512*512)

// Scratch (no cudaMalloc allowed)
__device__ float g_q[BTD], g_k[BTD], g_v[BTD];
__device__ float g_xr[BTD], g_t1[BTD], g_t2[BTD], g_ln[BTD];
__device__ float g_a1[BTD], g_a2[BTD];

// ---------------------------------------------------------------------------
// tf32 helpers
// ---------------------------------------------------------------------------
__device__ __forceinline__ unsigned cvt_tf32(float f) {
    unsigned u; asm("cvt.rna.tf32.f32 %0, %1;" : "=r"(u) : "f"(f)); return u;
}
__device__ __forceinline__ void split_tf32(float f, unsigned &hi, unsigned &lo) {
    hi = cvt_tf32(f);
    lo = cvt_tf32(f - __uint_as_float(hi));
}
__device__ __forceinline__ void mma_tf32(float* c, const unsigned* a, unsigned b0, unsigned b1) {
    asm volatile("mma.sync.aligned.m16n8k8.row.col.f32.tf32.tf32.f32 "
        "{%0,%1,%2,%3}, {%4,%5,%6,%7}, {%8,%9}, {%0,%1,%2,%3};"
        : "+f"(c[0]), "+f"(c[1]), "+f"(c[2]), "+f"(c[3])
        : "r"(a[0]), "r"(a[1]), "r"(a[2]), "r"(a[3]), "r"(b0), "r"(b1));
}

// ---------------------------------------------------------------------------
// Tensor-core GEMM: C(M,512) = A(M,512) @ W(512,512)^T + bias
// 128x128 CTA tile, 8 warps (32x64 warp tile), k-chunk 32, double-buffered.
// blockIdx.z selects one of up to 3 (A,W,b,C) sets. chunkMode: weight index
// = (m0%384)/128 for the T-chunked blocks 1..3. splitMask bit z: 3-mma
// hi/lo tf32 split for near-fp32 accuracy.
// ---------------------------------------------------------------------------
__global__ __launch_bounds__(256) void gemm_tc(
    const float* __restrict__ A0, const float* __restrict__ W0, const float* __restrict__ B0, float* __restrict__ C0,
    const float* __restrict__ A1, const float* __restrict__ W1, const float* __restrict__ B1, float* __restrict__ C1,
    const float* __restrict__ A2, const float* __restrict__ W2, const float* __restrict__ B2, float* __restrict__ C2,
    int chunkMode, int splitMask)
{
    extern __shared__ float sm[];
    float* As = sm;                 // [2][128*36]
    float* Ws = sm + 2*128*36;      // [2][128*36]
    const int z = blockIdx.z;
    const float* A  = (z==0) ? A0 : (z==1) ? A1 : A2;
    const float* W  = (z==0) ? W0 : (z==1) ? W1 : W2;
    const float* Bb = (z==0) ? B0 : (z==1) ? B1 : B2;
    float*       C  = (z==0) ? C0 : (z==1) ? C1 : C2;
    const bool split = (splitMask >> z) & 1;

    const int m0 = blockIdx.y * 128, n0 = blockIdx.x * 128;
    const int widx = chunkMode ? ((m0 % 384) / 128) : 0;
    const float* Wp = W + (size_t)widx * WKN;
    const float* bp = Bb + widx * 512;

    const int tid = threadIdx.x, lane = tid & 31, wid = tid >> 5;
    const int wm = wid & 3, wn = wid >> 2, qr = lane >> 2, qc = lane & 3;

    float acc[2][8][4];
#pragma unroll
    for (int mi = 0; mi < 2; mi++)
#pragma unroll
        for (int ni = 0; ni < 8; ni++)
#pragma unroll
            for (int j = 0; j < 4; j++) acc[mi][ni][j] = 0.f;

    auto loadTile = [&](int kt, int buf) {
        float* as = As + buf * (128*36);
        float* ws = Ws + buf * (128*36);
#pragma unroll
        for (int r = 0; r < 4; r++) {
            int idx = tid + r * 256;
            int row = idx >> 3, k4 = (idx & 7) * 4;
            float4 a = *(const float4*)(A  + (size_t)(m0 + row) * 512 + kt + k4);
            *(float4*)(as + row * 36 + k4) = a;
            float4 w = *(const float4*)(Wp + (size_t)(n0 + row) * 512 + kt + k4);
            *(float4*)(ws + row * 36 + k4) = w;
        }
    };

    loadTile(0, 0);
    __syncthreads();

    for (int kt = 0; kt < 16; kt++) {
        const int buf = kt & 1;
        if (kt < 15) loadTile((kt + 1) * 32, buf ^ 1);
        const float* as = As + buf * (128*36);
        const float* ws = Ws + buf * (128*36);
#pragma unroll
        for (int kk = 0; kk < 4; kk++) {
            const int col = kk * 8 + qc;
            unsigned ah[2][4], al[2][4];
#pragma unroll
            for (int mi = 0; mi < 2; mi++) {
                int row = wm * 32 + mi * 16 + qr;
                float f0 = as[row*36 + col];
                float f1 = as[(row+8)*36 + col];
                float f2 = as[row*36 + col + 4];
                float f3 = as[(row+8)*36 + col + 4];
                if (split) {
                    split_tf32(f0, ah[mi][0], al[mi][0]);
                    split_tf32(f1, ah[mi][1], al[mi][1]);
                    split_tf32(f2, ah[mi][2], al[mi][2]);
                    split_tf32(f3, ah[mi][3], al[mi][3]);
                } else {
                    ah[mi][0] = cvt_tf32(f0); ah[mi][1] = cvt_tf32(f1);
                    ah[mi][2] = cvt_tf32(f2); ah[mi][3] = cvt_tf32(f3);
                }
            }
#pragma unroll
            for (int ni = 0; ni < 8; ni++) {
                int nr = wn * 64 + ni * 8 + qr;
                float f0 = ws[nr*36 + col];
                float f1 = ws[nr*36 + col + 4];
                if (split) {
                    unsigned bh0, bl0, bh1, bl1;
                    split_tf32(f0, bh0, bl0);
                    split_tf32(f1, bh1, bl1);
#pragma unroll
                    for (int mi = 0; mi < 2; mi++) {
                        mma_tf32(acc[mi][ni], ah[mi], bh0, bh1);
                        mma_tf32(acc[mi][ni], ah[mi], bl0, bl1);
                        mma_tf32(acc[mi][ni], al[mi], bh0, bh1);
                    }
                } else {
                    unsigned b0 = cvt_tf32(f0), b1 = cvt_tf32(f1);
#pragma unroll
                    for (int mi = 0; mi < 2; mi++)
                        mma_tf32(acc[mi][ni], ah[mi], b0, b1);
                }
            }
        }
        __syncthreads();
    }

#pragma unroll
    for (int mi = 0; mi < 2; mi++) {
#pragma unroll
        for (int ni = 0; ni < 8; ni++) {
            int row = m0 + wm * 32 + mi * 16 + qr;
            int col = n0 + wn * 64 + ni * 8 + 2 * qc;
            float2 bb = *(const float2*)(bp + col);
            float2 v0 = { acc[mi][ni][0] + bb.x, acc[mi][ni][1] + bb.y };
            float2 v1 = { acc[mi][ni][2] + bb.x, acc[mi][ni][3] + bb.y };
            *(float2*)(C + (size_t)row * 512 + col)       = v0;
            *(float2*)(C + (size_t)(row + 8) * 512 + col) = v1;
        }
    }
}

// ---------------------------------------------------------------------------
// Tensor-core attention. One CTA per (b,h[,chunk]). 256 threads, 8 warps.
// Smem: Kt/Vt/Qt = transposed slabs [T][36] (Kt[t][i]=K[i][t]), Mv/Lv row
// stats, Ps = per-warp P^T scratch [16][20].
// Pass 1: warps over t16 tiles, sweep s in 64-chunks: S = K^T V via split-tf32
//         mma; online max/sumexp per row -> Mv, Lv=1/l.
// Pass 2: warps over s16 tiles, sweep t in 16-chunks: recompute S^T, P =
//         exp(S*scale - Mv)*Lv, roundtrip P through Ps, Out^T += P^T @ Q^T
//         via split mma. Epilogue adds optional addend.
// ---------------------------------------------------------------------------
__global__ __launch_bounds__(256) void attn_tc(
    const float* __restrict__ Qb, const float* __restrict__ Kb,
    const float* __restrict__ Vb, const float* __restrict__ temp,
    const float* __restrict__ addend, float* __restrict__ Ob,
    int T, int tempBase)
{
    extern __shared__ float sm[];
    float* Kt = sm;
    float* Vt = Kt + T * 36;
    float* Qt = Vt + T * 36;
    float* Mv = Qt + T * 36;
    float* Lv = Mv + T;
    float* Ps = Lv + T;   // 8 * 16 * 20

    const int h = blockIdx.x, c = blockIdx.y, b = blockIdx.z;
    const int tid = threadIdx.x, lane = tid & 31, wid = tid >> 5;
    const int qr = lane >> 2, qc = lane & 3;
    const size_t off = (size_t)b * (T_*D_) + (size_t)c * (128*D_) + (size_t)h * 32 * T;
    const float scale = temp[(tempBase + c) * H_ + h];

    for (int idx = tid; idx < 32 * T; idx += 256) {
        int i = idx / T, t = idx - i * T;
        Kt[t*36 + i] = Kb[off + (size_t)i * T + t];
        Vt[t*36 + i] = Vb[off + (size_t)i * T + t];
        Qt[t*36 + i] = Qb[off + (size_t)i * T + t];
    }
    __syncthreads();

    const int nb = T >> 4;

    // ---------------- Pass 1: row stats ----------------
    for (int tb = wid; tb < nb; tb += 8) {
        const int t0 = tb * 16;
        unsigned ah[4][4], al[4][4];
#pragma unroll
        for (int kk = 0; kk < 4; kk++) {
            int col = kk * 8 + qc, r0 = t0 + qr;
            split_tf32(Kt[r0*36 + col],       ah[kk][0], al[kk][0]);
            split_tf32(Kt[(r0+8)*36 + col],   ah[kk][1], al[kk][1]);
            split_tf32(Kt[r0*36 + col + 4],   ah[kk][2], al[kk][2]);
            split_tf32(Kt[(r0+8)*36 + col+4], ah[kk][3], al[kk][3]);
        }
        float m0 = -3.0e38f, m1 = -3.0e38f, l0 = 0.f, l1 = 0.f;
        for (int s0 = 0; s0 < T; s0 += 64) {
            float cc[8][4];
#pragma unroll
            for (int nt = 0; nt < 8; nt++)
#pragma unroll
                for (int j = 0; j < 4; j++) cc[nt][j] = 0.f;
#pragma unroll
            for (int kk = 0; kk < 4; kk++) {
                const int col = kk * 8 + qc;
#pragma unroll
                for (int nt = 0; nt < 8; nt++) {
                    int srow = s0 + nt * 8 + qr;
                    unsigned bh0, bl0, bh1, bl1;
                    split_tf32(Vt[srow*36 + col],     bh0, bl0);
                    split_tf32(Vt[srow*36 + col + 4], bh1, bl1);
                    mma_tf32(cc[nt], ah[kk], bh0, bh1);
                    mma_tf32(cc[nt], ah[kk], bl0, bl1);
                    mma_tf32(cc[nt], al[kk], bh0, bh1);
                }
            }
            float cm0 = -3.0e38f, cm1 = -3.0e38f;
#pragma unroll
            for (int nt = 0; nt < 8; nt++) {
#pragma unroll
                for (int j = 0; j < 4; j++) cc[nt][j] *= scale;
                cm0 = fmaxf(cm0, fmaxf(cc[nt][0], cc[nt][1]));
                cm1 = fmaxf(cm1, fmaxf(cc[nt][2], cc[nt][3]));
            }
            cm0 = fmaxf(cm0, __shfl_xor_sync(0xffffffffu, cm0, 1));
            cm0 = fmaxf(cm0, __shfl_xor_sync(0xffffffffu, cm0, 2));
            cm1 = fmaxf(cm1, __shfl_xor_sync(0xffffffffu, cm1, 1));
            cm1 = fmaxf(cm1, __shfl_xor_sync(0xffffffffu, cm1, 2));
            float M0 = fmaxf(m0, cm0), M1 = fmaxf(m1, cm1);
            float p0 = 0.f, p1 = 0.f;
#pragma unroll
            for (int nt = 0; nt < 8; nt++) {
                p0 += __expf(cc[nt][0] - M0) + __expf(cc[nt][1] - M0);
                p1 += __expf(cc[nt][2] - M1) + __expf(cc[nt][3] - M1);
            }
            p0 += __shfl_xor_sync(0xffffffffu, p0, 1);
            p0 += __shfl_xor_sync(0xffffffffu, p0, 2);
            p1 += __shfl_xor_sync(0xffffffffu, p1, 1);
            p1 += __shfl_xor_sync(0xffffffffu, p1, 2);
            l0 = l0 * __expf(m0 - M0) + p0;  m0 = M0;
            l1 = l1 * __expf(m1 - M1) + p1;  m1 = M1;
        }
        if (qc == 0) {
            Mv[t0 + qr]     = m0;  Lv[t0 + qr]     = 1.f / l0;
            Mv[t0 + qr + 8] = m1;  Lv[t0 + qr + 8] = 1.f / l1;
        }
    }
    __syncthreads();

    // ---------------- Pass 2: output ----------------
    float* Pw = Ps + wid * (16 * 20);
    for (int sb = wid; sb < nb; sb += 8) {
        const int s0 = sb * 16;
        unsigned ah[4][4], al[4][4];
#pragma unroll
        for (int kk = 0; kk < 4; kk++) {
            int col = kk * 8 + qc, r0 = s0 + qr;
            split_tf32(Vt[r0*36 + col],       ah[kk][0], al[kk][0]);
            split_tf32(Vt[(r0+8)*36 + col],   ah[kk][1], al[kk][1]);
            split_tf32(Vt[r0*36 + col + 4],   ah[kk][2], al[kk][2]);
            split_tf32(Vt[(r0+8)*36 + col+4], ah[kk][3], al[kk][3]);
        }
        float o[4][4];
#pragma unroll
        for (int ni = 0; ni < 4; ni++)
#pragma unroll
            for (int j = 0; j < 4; j++) o[ni][j] = 0.f;

        for (int t0 = 0; t0 < T; t0 += 16) {
            float e[2][4];
#pragma unroll
            for (int nt = 0; nt < 2; nt++)
#pragma unroll
                for (int j = 0; j < 4; j++) e[nt][j] = 0.f;
#pragma unroll
            for (int kk = 0; kk < 4; kk++) {
                const int col = kk * 8 + qc;
#pragma unroll
                for (int nt = 0; nt < 2; nt++) {
                    int trow = t0 + nt * 8 + qr;
                    unsigned bh0, bl0, bh1, bl1;
                    split_tf32(Kt[trow*36 + col],     bh0, bl0);
                    split_tf32(Kt[trow*36 + col + 4], bh1, bl1);
                    mma_tf32(e[nt], ah[kk], bh0, bh1);
                    mma_tf32(e[nt], ah[kk], bl0, bl1);
                    mma_tf32(e[nt], al[kk], bh0, bh1);
                }
            }
#pragma unroll
            for (int nt = 0; nt < 2; nt++) {
                int tc = t0 + nt * 8 + 2 * qc;
                float mva = Mv[tc],   lva = Lv[tc];
                float mvb = Mv[tc+1], lvb = Lv[tc+1];
                e[nt][0] = __expf(e[nt][0] * scale - mva) * lva;
                e[nt][1] = __expf(e[nt][1] * scale - mvb) * lvb;
                e[nt][2] = __expf(e[nt][2] * scale - mva) * lva;
                e[nt][3] = __expf(e[nt][3] * scale - mvb) * lvb;
            }
            __syncwarp();
#pragma unroll
            for (int nt = 0; nt < 2; nt++) {
                Pw[qr*20     + nt*8 + 2*qc]     = e[nt][0];
                Pw[qr*20     + nt*8 + 2*qc + 1] = e[nt][1];
                Pw[(qr+8)*20 + nt*8 + 2*qc]     = e[nt][2];
                Pw[(qr+8)*20 + nt*8 + 2*qc + 1] = e[nt][3];
            }
            __syncwarp();
#pragma unroll
            for (int k2 = 0; k2 < 2; k2++) {
                unsigned ph[4], pl[4];
                split_tf32(Pw[qr*20     + k2*8 + qc],     ph[0], pl[0]);
                split_tf32(Pw[(qr+8)*20 + k2*8 + qc],     ph[1], pl[1]);
                split_tf32(Pw[qr*20     + k2*8 + qc + 4], ph[2], pl[2]);
                split_tf32(Pw[(qr+8)*20 + k2*8 + qc + 4], ph[3], pl[3]);
#pragma unroll
                for (int ni = 0; ni < 4; ni++) {
                    unsigned bh0, bl0, bh1, bl1;
                    split_tf32(Qt[(t0 + k2*8 + qc)*36     + ni*8 + qr], bh0, bl0);
                    split_tf32(Qt[(t0 + k2*8 + qc + 4)*36 + ni*8 + qr], bh1, bl1);
                    mma_tf32(o[ni], ph, bh0, bh1);
                    mma_tf32(o[ni], ph, bl0, bl1);
                    mma_tf32(o[ni], pl, bh0, bh1);
                }
            }
        }
        // epilogue: Out^T[s][i] (+ addend)
#pragma unroll
        for (int ni = 0; ni < 4; ni++) {
            int icol = ni * 8 + 2 * qc;
            int srow = s0 + qr;
            size_t base = off + (size_t)icol * T + srow;
            if (addend != nullptr) {
                Ob[base]         = o[ni][0] + addend[base];
                Ob[base + T]     = o[ni][1] + addend[base + T];
                Ob[base + 8]     = o[ni][2] + addend[base + 8];
                Ob[base + T + 8] = o[ni][3] + addend[base + T + 8];
            } else {
                Ob[base]         = o[ni][0];
                Ob[base + T]     = o[ni][1];
                Ob[base + 8]     = o[ni][2];
                Ob[base + T + 8] = o[ni][3];
            }
        }
    }
}

// ---------------------------------------------------------------------------
// LayerNorm: one warp per 512-wide row.
// ---------------------------------------------------------------------------
__global__ __launch_bounds__(256) void ln_kernel(
    const float* __restrict__ X, const float* __restrict__ gw,
    const float* __restrict__ gb, float* __restrict__ Y)
{
    const int row  = blockIdx.x * 8 + (threadIdx.x >> 5);
    const int lane = threadIdx.x & 31;
    const float4* xr = (const float4*)(X + (size_t)row * D_);
    float4 v[4];
    float s = 0.f, ss = 0.f;
#pragma unroll
    for (int w = 0; w < 4; w++) {
        v[w] = xr[w*32 + lane];
        s  += v[w].x + v[w].y + v[w].z + v[w].w;
        ss += v[w].x*v[w].x + v[w].y*v[w].y + v[w].z*v[w].z + v[w].w*v[w].w;
    }
#pragma unroll
    for (int o = 16; o > 0; o >>= 1) {
        s  += __shfl_xor_sync(0xffffffffu, s, o);
        ss += __shfl_xor_sync(0xffffffffu, ss, o);
    }
    const float mean = s * (1.f/512.f);
    const float var  = ss * (1.f/512.f) - mean*mean;
    const float r = rsqrtf(var + 1e-5f);
    float4* yr = (float4*)(Y + (size_t)row * D_);
    const float4* gr = (const float4*)gw;
    const float4* br = (const float4*)gb;
#pragma unroll
    for (int w = 0; w < 4; w++) {
        float4 gv = gr[w*32 + lane];
        float4 bv = br[w*32 + lane];
        float4 o;
        o.x = (v[w].x - mean) * r * gv.x + bv.x;
        o.y = (v[w].y - mean) * r * gv.y + bv.y;
        o.z = (v[w].z - mean) * r * gv.z + bv.z;
        o.w = (v[w].w - mean) * r * gv.w + bv.w;
        yr[w*32 + lane] = o;
    }
}

// ---------------------------------------------------------------------------
// Fusion gating
// ---------------------------------------------------------------------------
__device__ __forceinline__ float fuse1(float x1, float x2, float y1, float y2) {
    float mx = fmaxf(y1, y2);
    float e1 = __expf(y1 - mx), e2 = __expf(y2 - mx);
    return (x1*e1 + x2*e2) / (e1 + e2);
}

__global__ __launch_bounds__(256) void fuse_kernel(
    const float4* __restrict__ t1, const float4* __restrict__ t2,
    const float4* __restrict__ a1, const float4* __restrict__ a2,
    float4* __restrict__ out)
{
    int i = blockIdx.x * 256 + threadIdx.x;
    float4 x1 = t1[i], x2 = t2[i], y1 = a1[i], y2 = a2[i];
    float4 o;
    o.x = fuse1(x1.x, x2.x, y1.x, y2.x);
    o.y = fuse1(x1.y, x2.y, y1.y, y2.y);
    o.z = fuse1(x1.z, x2.z, y1.z, y2.z);
    o.w = fuse1(x1.w, x2.w, y1.w, y2.w);
    out[i] = o;
}

// ---------------------------------------------------------------------------
extern "C" void kernel_launch(void* const* d_in, const int* in_sizes, int n_in,
                              void* d_out, int out_size)
{
    (void)in_sizes; (void)n_in; (void)out_size;
    const float* x    = (const float*)d_in[0];
    const float* qw   = (const float*)d_in[1];
    const float* qb   = (const float*)d_in[2];
    const float* kw   = (const float*)d_in[3];
    const float* kb   = (const float*)d_in[4];
    const float* vw   = (const float*)d_in[5];
    const float* vb   = (const float*)d_in[6];
    const float* temp = (const float*)d_in[7];
    const float* lng  = (const float*)d_in[8];
    const float* lnb  = (const float*)d_in[9];
    const float* fw   = (const float*)d_in[10];
    const float* fb   = (const float*)d_in[11];
    float* out = (float*)d_out;

    float *q, *k, *v, *xr, *t1, *t2, *ln, *a1, *a2;
    cudaGetSymbolAddress((void**)&q,  g_q);
    cudaGetSymbolAddress((void**)&k,  g_k);
    cudaGetSymbolAddress((void**)&v,  g_v);
    cudaGetSymbolAddress((void**)&xr, g_xr);
    cudaGetSymbolAddress((void**)&t1, g_t1);
    cudaGetSymbolAddress((void**)&t2, g_t2);
    cudaGetSymbolAddress((void**)&ln, g_ln);
    cudaGetSymbolAddress((void**)&a1, g_a1);
    cudaGetSymbolAddress((void**)&a2, g_a2);

    const int gemmSmem = 2 * 2 * 128 * 36 * 4;                    // 73728
    const int smem384  = (3*384*36 + 2*384 + 8*16*20) * 4;        // 179200
    const int smem128  = (3*128*36 + 2*128 + 8*16*20) * 4;        // 66560
    cudaFuncSetAttribute(gemm_tc, cudaFuncAttributeMaxDynamicSharedMemorySize, gemmSmem);
    cudaFuncSetAttribute(attn_tc, cudaFuncAttributeMaxDynamicSharedMemorySize, smem384);

    dim3 gg3(4, 96, 3);

    // Block 0: QKV projections (split for K,V) + attention -> xr
    gemm_tc<<<gg3, 256, gemmSmem>>>(x, qw, qb, q,  x, kw, kb, k,  x, vw, vb, v, 0, 6);
    attn_tc<<<dim3(H_, 1, B_), 256, smem384>>>(q, k, v, temp, nullptr, xr, 384, 0);

    // Blocks 1-3 (T chunks of 128): batched QKV + chunked attention -> t1
    gemm_tc<<<gg3, 256, gemmSmem>>>(x, qw + WKN, qb + 512, q,
                                    x, kw + WKN, kb + 512, k,
                                    x, vw + WKN, vb + 512, v, 1, 6);
    attn_tc<<<dim3(H_, 3, B_), 256, smem128>>>(q, k, v, temp, xr, t1, 128, 1);

    // LayerNorm(tmp1)
    ln_kernel<<<M_/8, 256>>>(t1, lng, lnb, ln);

    // Block 4: QKV on LN output + attention -> t2
    gemm_tc<<<gg3, 256, gemmSmem>>>(ln, qw + 4*WKN, qb + 4*512, q,
                                    ln, kw + 4*WKN, kb + 4*512, k,
                                    ln, vw + 4*WKN, vb + 4*512, v, 0, 6);
    attn_tc<<<dim3(H_, 1, B_), 256, smem384>>>(q, k, v, temp, xr, t2, 384, 4);

    // Fusion gating logits (no split needed) + combine
    gemm_tc<<<dim3(4, 96, 2), 256, gemmSmem>>>(t1, fw, fb, a1,
                                               t2, fw, fb, a2,
                                               t2, fw, fb, a2, 0, 0);
    fuse_kernel<<<BTD/4/256, 256>>>((const float4*)t1, (const float4*)t2,
                                    (const float4*)a1, (const float4*)a2, (float4*)out);
}

// round 4
// speedup vs baseline: 2.2291x; 1.3216x over previous
#include <cuda_runtime.h>
#include <cuda_fp16.h>
#include <math.h>

#define B_  32
#define T_  384
#define D_  512
#define H_  16
#define BTD (B_*T_*D_)     // 6291456
#define M_  (B_*T_)        // 12288
#define WKN (512*512)

// Scratch (no cudaMalloc allowed)
__device__ float g_q[BTD], g_k[BTD], g_v[BTD];
__device__ float g_q2[BTD], g_k2[BTD], g_v2[BTD];
__device__ float g_xr[BTD], g_t1[BTD], g_t2[BTD], g_ln[BTD];
__device__ float g_a1[BTD], g_a2[BTD];

// ---------------------------------------------------------------------------
// fp16 helpers
// ---------------------------------------------------------------------------
__device__ __forceinline__ void split_h(float x, __half& hi, __half& lo) {
    hi = __float2half_rn(x);
    lo = __float2half_rn(x - __half2float(hi));
}
__device__ __forceinline__ unsigned pack2(__half a, __half b) {
    __half2 h = __halves2half2(a, b);
    return *reinterpret_cast<unsigned*>(&h);
}
__device__ __forceinline__ void mma_f16(float* c, const unsigned* a, unsigned b0, unsigned b1) {
    asm volatile("mma.sync.aligned.m16n8k16.row.col.f32.f16.f16.f32 "
        "{%0,%1,%2,%3}, {%4,%5,%6,%7}, {%8,%9}, {%0,%1,%2,%3};"
        : "+f"(c[0]), "+f"(c[1]), "+f"(c[2]), "+f"(c[3])
        : "r"(a[0]), "r"(a[1]), "r"(a[2]), "r"(a[3]), "r"(b0), "r"(b1));
}
__device__ __forceinline__ unsigned lduh2(const __half* p) {
    return *reinterpret_cast<const unsigned*>(p);
}

// ---------------------------------------------------------------------------
// fp16-split GEMM: C(M,512) = A(M,512) @ W(512,512)^T + bias
// 128x128 CTA tile, 8 warps (32m x 64n warp tile), k-chunk 32, double-buffer.
// Split (hi/lo fp16) computed ONCE at tile load; inner loop = LDS + HMMA only.
// Up to 6 independent (A,W,bias,C) slices via blockIdx.z; chunk flag selects
// weight index (m0%384)/128 for the T-chunked blocks.
// ---------------------------------------------------------------------------
struct GSlice { const float* A; const float* W; const float* b; float* C; int chunk; };
struct GArgs  { GSlice s[6]; };

#define GS 5120   // halves per (tensor,buf): 128*40

__global__ __launch_bounds__(256) void gemm_tc(GArgs ga)
{
    extern __shared__ __half smh[];
    __half* Ahi = smh;            // [2][128*40]
    __half* Alo = smh + 2*GS;
    __half* Whi = smh + 4*GS;
    __half* Wlo = smh + 6*GS;

    const GSlice sl = ga.s[blockIdx.z];
    const int m0 = blockIdx.y * 128, n0 = blockIdx.x * 128;
    const int widx = sl.chunk ? ((m0 % 384) / 128) : 0;
    const float* A  = sl.A;
    const float* Wp = sl.W + (size_t)widx * WKN;
    const float* bp = sl.b + widx * 512;
    float* C = sl.C;

    const int tid = threadIdx.x, lane = tid & 31, wid = tid >> 5;
    const int wm = wid & 3, wn = wid >> 2, qr = lane >> 2, qc = lane & 3;

    float acc[2][8][4];
#pragma unroll
    for (int mi = 0; mi < 2; mi++)
#pragma unroll
        for (int ni = 0; ni < 8; ni++)
#pragma unroll
            for (int j = 0; j < 4; j++) acc[mi][ni][j] = 0.f;

    auto loadTile = [&](int kt, int buf) {
#pragma unroll
        for (int r = 0; r < 2; r++) {
            int idx = tid + r * 256;
            int row = idx >> 2, k8 = (idx & 3) * 8;   // 8 floats per thread
            const float4* ap = (const float4*)(A  + (size_t)(m0 + row) * 512 + kt + k8);
            const float4* wp = (const float4*)(Wp + (size_t)(n0 + row) * 512 + kt + k8);
            float4 a0 = ap[0], a1 = ap[1];
            float4 w0 = wp[0], w1 = wp[1];
            int base = buf * GS + row * 40 + k8;
            __half h, l;
            float av[8] = {a0.x,a0.y,a0.z,a0.w,a1.x,a1.y,a1.z,a1.w};
            float wv[8] = {w0.x,w0.y,w0.z,w0.w,w1.x,w1.y,w1.z,w1.w};
#pragma unroll
            for (int j = 0; j < 8; j++) {
                split_h(av[j], h, l); Ahi[base+j] = h; Alo[base+j] = l;
                split_h(wv[j], h, l); Whi[base+j] = h; Wlo[base+j] = l;
            }
        }
    };

    loadTile(0, 0);
    __syncthreads();

    for (int kt = 0; kt < 16; kt++) {
        const int buf = kt & 1;
        if (kt < 15) loadTile((kt + 1) * 32, buf ^ 1);
        const int bo = buf * GS;
#pragma unroll
        for (int ks = 0; ks < 2; ks++) {
            const int kb = ks * 16 + 2 * qc;
            unsigned ah[2][4], al[2][4];
#pragma unroll
            for (int mi = 0; mi < 2; mi++) {
                int rb = wm * 32 + mi * 16;
                ah[mi][0] = lduh2(Ahi + bo + (rb+qr  )*40 + kb);
                ah[mi][1] = lduh2(Ahi + bo + (rb+qr+8)*40 + kb);
                ah[mi][2] = lduh2(Ahi + bo + (rb+qr  )*40 + kb + 8);
                ah[mi][3] = lduh2(Ahi + bo + (rb+qr+8)*40 + kb + 8);
                al[mi][0] = lduh2(Alo + bo + (rb+qr  )*40 + kb);
                al[mi][1] = lduh2(Alo + bo + (rb+qr+8)*40 + kb);
                al[mi][2] = lduh2(Alo + bo + (rb+qr  )*40 + kb + 8);
                al[mi][3] = lduh2(Alo + bo + (rb+qr+8)*40 + kb + 8);
            }
#pragma unroll
            for (int ni = 0; ni < 8; ni++) {
                int nr = wn * 64 + ni * 8 + qr;
                unsigned bh0 = lduh2(Whi + bo + nr*40 + kb);
                unsigned bh1 = lduh2(Whi + bo + nr*40 + kb + 8);
                unsigned bl0 = lduh2(Wlo + bo + nr*40 + kb);
                unsigned bl1 = lduh2(Wlo + bo + nr*40 + kb + 8);
#pragma unroll
                for (int mi = 0; mi < 2; mi++) {
                    mma_f16(acc[mi][ni], ah[mi], bh0, bh1);
                    mma_f16(acc[mi][ni], ah[mi], bl0, bl1);
                    mma_f16(acc[mi][ni], al[mi], bh0, bh1);
                }
            }
        }
        __syncthreads();
    }

#pragma unroll
    for (int mi = 0; mi < 2; mi++) {
#pragma unroll
        for (int ni = 0; ni < 8; ni++) {
            int row = m0 + wm * 32 + mi * 16 + qr;
            int col = n0 + wn * 64 + ni * 8 + 2 * qc;
            float2 bb = *(const float2*)(bp + col);
            float2 v0 = { acc[mi][ni][0] + bb.x, acc[mi][ni][1] + bb.y };
            float2 v1 = { acc[mi][ni][2] + bb.x, acc[mi][ni][3] + bb.y };
            *(float2*)(C + (size_t)row * 512 + col)       = v0;
            *(float2*)(C + (size_t)(row + 8) * 512 + col) = v1;
        }
    }
}

// ---------------------------------------------------------------------------
// fp16-split tensor-core attention. One CTA per (b,h[,chunk]), 8 warps.
// All of K^T, V^T (t-major, [T][36]) and Q ([32][T+8]) are split hi/lo to
// SMEM once. Pass 1: S=K^T V row stats (online max/sum). Pass 2: recompute
// S^T, P=exp(..), P split through per-warp scratch, O^T += P^T Q^T.
// ---------------------------------------------------------------------------
__global__ __launch_bounds__(256) void attn_tc(
    const float* __restrict__ Qb, const float* __restrict__ Kb,
    const float* __restrict__ Vb, const float* __restrict__ temp,
    const float* __restrict__ addend, float* __restrict__ Ob,
    int T, int tempBase)
{
    extern __shared__ __half smh[];
    const int QS = T + 8;
    __half* Khi = smh;
    __half* Klo = Khi + T * 36;
    __half* Vhi = Klo + T * 36;
    __half* Vlo = Vhi + T * 36;
    __half* Qhi = Vlo + T * 36;
    __half* Qlo = Qhi + 32 * QS;
    float*  Mv  = (float*)(Qlo + 32 * QS);
    float*  Lv  = Mv + T;
    __half* Pshi = (__half*)(Lv + T);       // 8 warps * 16*24
    __half* Pslo = Pshi + 8 * 16 * 24;

    const int h = blockIdx.x, c = blockIdx.y, b = blockIdx.z;
    const int tid = threadIdx.x, lane = tid & 31, wid = tid >> 5;
    const int qr = lane >> 2, qc = lane & 3;
    const size_t off = (size_t)b * (T_*D_) + (size_t)c * (128*D_) + (size_t)h * 32 * T;
    const float scale = temp[(tempBase + c) * H_ + h];

    for (int idx = tid; idx < 32 * T; idx += 256) {
        int i = idx / T, t = idx - i * T;
        __half hi, lo;
        split_h(Kb[off + idx], hi, lo);
        Khi[t*36 + i] = hi; Klo[t*36 + i] = lo;
        split_h(Vb[off + idx], hi, lo);
        Vhi[t*36 + i] = hi; Vlo[t*36 + i] = lo;
        split_h(Qb[off + idx], hi, lo);
        Qhi[i*QS + t] = hi; Qlo[i*QS + t] = lo;
    }
    __syncthreads();

    const int nb = T >> 4;

    // ---------------- Pass 1: row stats ----------------
    for (int tb = wid; tb < nb; tb += 8) {
        const int t0 = tb * 16;
        unsigned ah[2][4], al[2][4];
#pragma unroll
        for (int ks = 0; ks < 2; ks++) {
            const int kb = ks * 16 + 2 * qc;
            ah[ks][0] = lduh2(Khi + (t0+qr  )*36 + kb);
            ah[ks][1] = lduh2(Khi + (t0+qr+8)*36 + kb);
            ah[ks][2] = lduh2(Khi + (t0+qr  )*36 + kb + 8);
            ah[ks][3] = lduh2(Khi + (t0+qr+8)*36 + kb + 8);
            al[ks][0] = lduh2(Klo + (t0+qr  )*36 + kb);
            al[ks][1] = lduh2(Klo + (t0+qr+8)*36 + kb);
            al[ks][2] = lduh2(Klo + (t0+qr  )*36 + kb + 8);
            al[ks][3] = lduh2(Klo + (t0+qr+8)*36 + kb + 8);
        }
        float m0 = -3.0e38f, m1 = -3.0e38f, l0 = 0.f, l1 = 0.f;
        for (int s0 = 0; s0 < T; s0 += 64) {
            float cc[8][4];
#pragma unroll
            for (int nt = 0; nt < 8; nt++)
#pragma unroll
                for (int j = 0; j < 4; j++) cc[nt][j] = 0.f;
#pragma unroll
            for (int ks = 0; ks < 2; ks++) {
                const int kb = ks * 16 + 2 * qc;
#pragma unroll
                for (int nt = 0; nt < 8; nt++) {
                    int sr = s0 + nt * 8 + qr;
                    unsigned bh0 = lduh2(Vhi + sr*36 + kb);
                    unsigned bh1 = lduh2(Vhi + sr*36 + kb + 8);
                    unsigned bl0 = lduh2(Vlo + sr*36 + kb);
                    unsigned bl1 = lduh2(Vlo + sr*36 + kb + 8);
                    mma_f16(cc[nt], ah[ks], bh0, bh1);
                    mma_f16(cc[nt], ah[ks], bl0, bl1);
                    mma_f16(cc[nt], al[ks], bh0, bh1);
                }
            }
            float cm0 = -3.0e38f, cm1 = -3.0e38f;
#pragma unroll
            for (int nt = 0; nt < 8; nt++) {
#pragma unroll
                for (int j = 0; j < 4; j++) cc[nt][j] *= scale;
                cm0 = fmaxf(cm0, fmaxf(cc[nt][0], cc[nt][1]));
                cm1 = fmaxf(cm1, fmaxf(cc[nt][2], cc[nt][3]));
            }
            cm0 = fmaxf(cm0, __shfl_xor_sync(0xffffffffu, cm0, 1));
            cm0 = fmaxf(cm0, __shfl_xor_sync(0xffffffffu, cm0, 2));
            cm1 = fmaxf(cm1, __shfl_xor_sync(0xffffffffu, cm1, 1));
            cm1 = fmaxf(cm1, __shfl_xor_sync(0xffffffffu, cm1, 2));
            float M0 = fmaxf(m0, cm0), M1 = fmaxf(m1, cm1);
            float p0 = 0.f, p1 = 0.f;
#pragma unroll
            for (int nt = 0; nt < 8; nt++) {
                p0 += __expf(cc[nt][0] - M0) + __expf(cc[nt][1] - M0);
                p1 += __expf(cc[nt][2] - M1) + __expf(cc[nt][3] - M1);
            }
            p0 += __shfl_xor_sync(0xffffffffu, p0, 1);
            p0 += __shfl_xor_sync(0xffffffffu, p0, 2);
            p1 += __shfl_xor_sync(0xffffffffu, p1, 1);
            p1 += __shfl_xor_sync(0xffffffffu, p1, 2);
            l0 = l0 * __expf(m0 - M0) + p0;  m0 = M0;
            l1 = l1 * __expf(m1 - M1) + p1;  m1 = M1;
        }
        if (qc == 0) {
            Mv[t0 + qr]     = m0;  Lv[t0 + qr]     = 1.f / l0;
            Mv[t0 + qr + 8] = m1;  Lv[t0 + qr + 8] = 1.f / l1;
        }
    }
    __syncthreads();

    // ---------------- Pass 2: output ----------------
    __half* Pwh = Pshi + wid * (16 * 24);
    __half* Pwl = Pslo + wid * (16 * 24);
    for (int sb = wid; sb < nb; sb += 8) {
        const int s0 = sb * 16;
        unsigned vh[2][4], vl[2][4];
#pragma unroll
        for (int ks = 0; ks < 2; ks++) {
            const int kb = ks * 16 + 2 * qc;
            vh[ks][0] = lduh2(Vhi + (s0+qr  )*36 + kb);
            vh[ks][1] = lduh2(Vhi + (s0+qr+8)*36 + kb);
            vh[ks][2] = lduh2(Vhi + (s0+qr  )*36 + kb + 8);
            vh[ks][3] = lduh2(Vhi + (s0+qr+8)*36 + kb + 8);
            vl[ks][0] = lduh2(Vlo + (s0+qr  )*36 + kb);
            vl[ks][1] = lduh2(Vlo + (s0+qr+8)*36 + kb);
            vl[ks][2] = lduh2(Vlo + (s0+qr  )*36 + kb + 8);
            vl[ks][3] = lduh2(Vlo + (s0+qr+8)*36 + kb + 8);
        }
        float o[4][4];
#pragma unroll
        for (int ni = 0; ni < 4; ni++)
#pragma unroll
            for (int j = 0; j < 4; j++) o[ni][j] = 0.f;

        for (int t0 = 0; t0 < T; t0 += 16) {
            float e[2][4];
#pragma unroll
            for (int nt = 0; nt < 2; nt++)
#pragma unroll
                for (int j = 0; j < 4; j++) e[nt][j] = 0.f;
#pragma unroll
            for (int ks = 0; ks < 2; ks++) {
                const int kb = ks * 16 + 2 * qc;
#pragma unroll
                for (int nt = 0; nt < 2; nt++) {
                    int tr = t0 + nt * 8 + qr;
                    unsigned bh0 = lduh2(Khi + tr*36 + kb);
                    unsigned bh1 = lduh2(Khi + tr*36 + kb + 8);
                    unsigned bl0 = lduh2(Klo + tr*36 + kb);
                    unsigned bl1 = lduh2(Klo + tr*36 + kb + 8);
                    mma_f16(e[nt], vh[ks], bh0, bh1);
                    mma_f16(e[nt], vh[ks], bl0, bl1);
                    mma_f16(e[nt], vl[ks], bh0, bh1);
                }
            }
            __syncwarp();
#pragma unroll
            for (int nt = 0; nt < 2; nt++) {
                int tc = t0 + nt * 8 + 2 * qc;
                float mva = Mv[tc],   lva = Lv[tc];
                float mvb = Mv[tc+1], lvb = Lv[tc+1];
                float e0 = __expf(e[nt][0] * scale - mva) * lva;
                float e1 = __expf(e[nt][1] * scale - mvb) * lvb;
                float e2 = __expf(e[nt][2] * scale - mva) * lva;
                float e3 = __expf(e[nt][3] * scale - mvb) * lvb;
                __half h0, h1, h2, h3, g0, g1, g2, g3;
                split_h(e0, h0, g0); split_h(e1, h1, g1);
                split_h(e2, h2, g2); split_h(e3, h3, g3);
                *(unsigned*)(Pwh + qr*24     + nt*8 + 2*qc) = pack2(h0, h1);
                *(unsigned*)(Pwh + (qr+8)*24 + nt*8 + 2*qc) = pack2(h2, h3);
                *(unsigned*)(Pwl + qr*24     + nt*8 + 2*qc) = pack2(g0, g1);
                *(unsigned*)(Pwl + (qr+8)*24 + nt*8 + 2*qc) = pack2(g2, g3);
            }
            __syncwarp();
            unsigned ph[4], pl[4];
            ph[0] = lduh2(Pwh + qr*24     + 2*qc);
            ph[1] = lduh2(Pwh + (qr+8)*24 + 2*qc);
            ph[2] = lduh2(Pwh + qr*24     + 2*qc + 8);
            ph[3] = lduh2(Pwh + (qr+8)*24 + 2*qc + 8);
            pl[0] = lduh2(Pwl + qr*24     + 2*qc);
            pl[1] = lduh2(Pwl + (qr+8)*24 + 2*qc);
            pl[2] = lduh2(Pwl + qr*24     + 2*qc + 8);
            pl[3] = lduh2(Pwl + (qr+8)*24 + 2*qc + 8);
#pragma unroll
            for (int ni = 0; ni < 4; ni++) {
                int ir = ni * 8 + qr;
                unsigned qb0 = lduh2(Qhi + ir*QS + t0 + 2*qc);
                unsigned qb1 = lduh2(Qhi + ir*QS + t0 + 2*qc + 8);
                unsigned ql0 = lduh2(Qlo + ir*QS + t0 + 2*qc);
                unsigned ql1 = lduh2(Qlo + ir*QS + t0 + 2*qc + 8);
                mma_f16(o[ni], ph, qb0, qb1);
                mma_f16(o[ni], ph, ql0, ql1);
                mma_f16(o[ni], pl, qb0, qb1);
            }
        }
        // epilogue: Out^T[s][i] (+ addend)
#pragma unroll
        for (int ni = 0; ni < 4; ni++) {
            int icol = ni * 8 + 2 * qc;
            int srow = s0 + qr;
            size_t base = off + (size_t)icol * T + srow;
            if (addend != nullptr) {
                Ob[base]         = o[ni][0] + addend[base];
                Ob[base + T]     = o[ni][1] + addend[base + T];
                Ob[base + 8]     = o[ni][2] + addend[base + 8];
                Ob[base + T + 8] = o[ni][3] + addend[base + T + 8];
            } else {
                Ob[base]         = o[ni][0];
                Ob[base + T]     = o[ni][1];
                Ob[base + 8]     = o[ni][2];
                Ob[base + T + 8] = o[ni][3];
            }
        }
    }
}

// ---------------------------------------------------------------------------
// LayerNorm: one warp per 512-wide row.
// ---------------------------------------------------------------------------
__global__ __launch_bounds__(256) void ln_kernel(
    const float* __restrict__ X, const float* __restrict__ gw,
    const float* __restrict__ gb, float* __restrict__ Y)
{
    const int row  = blockIdx.x * 8 + (threadIdx.x >> 5);
    const int lane = threadIdx.x & 31;
    const float4* xr = (const float4*)(X + (size_t)row * D_);
    float4 v[4];
    float s = 0.f, ss = 0.f;
#pragma unroll
    for (int w = 0; w < 4; w++) {
        v[w] = xr[w*32 + lane];
        s  += v[w].x + v[w].y + v[w].z + v[w].w;
        ss += v[w].x*v[w].x + v[w].y*v[w].y + v[w].z*v[w].z + v[w].w*v[w].w;
    }
#pragma unroll
    for (int o = 16; o > 0; o >>= 1) {
        s  += __shfl_xor_sync(0xffffffffu, s, o);
        ss += __shfl_xor_sync(0xffffffffu, ss, o);
    }
    const float mean = s * (1.f/512.f);
    const float var  = ss * (1.f/512.f) - mean*mean;
    const float r = rsqrtf(var + 1e-5f);
    float4* yr = (float4*)(Y + (size_t)row * D_);
    const float4* gr = (const float4*)gw;
    const float4* br = (const float4*)gb;
#pragma unroll
    for (int w = 0; w < 4; w++) {
        float4 gv = gr[w*32 + lane];
        float4 bv = br[w*32 + lane];
        float4 o;
        o.x = (v[w].x - mean) * r * gv.x + bv.x;
        o.y = (v[w].y - mean) * r * gv.y + bv.y;
        o.z = (v[w].z - mean) * r * gv.z + bv.z;
        o.w = (v[w].w - mean) * r * gv.w + bv.w;
        yr[w*32 + lane] = o;
    }
}

// ---------------------------------------------------------------------------
// Fusion gating
// ---------------------------------------------------------------------------
__device__ __forceinline__ float fuse1(float x1, float x2, float y1, float y2) {
    float mx = fmaxf(y1, y2);
    float e1 = __expf(y1 - mx), e2 = __expf(y2 - mx);
    return (x1*e1 + x2*e2) / (e1 + e2);
}

__global__ __launch_bounds__(256) void fuse_kernel(
    const float4* __restrict__ t1, const float4* __restrict__ t2,
    const float4* __restrict__ a1, const float4* __restrict__ a2,
    float4* __restrict__ out)
{
    int i = blockIdx.x * 256 + threadIdx.x;
    float4 x1 = t1[i], x2 = t2[i], y1 = a1[i], y2 = a2[i];
    float4 o;
    o.x = fuse1(x1.x, x2.x, y1.x, y2.x);
    o.y = fuse1(x1.y, x2.y, y1.y, y2.y);
    o.z = fuse1(x1.z, x2.z, y1.z, y2.z);
    o.w = fuse1(x1.w, x2.w, y1.w, y2.w);
    out[i] = o;
}

// ---------------------------------------------------------------------------
extern "C" void kernel_launch(void* const* d_in, const int* in_sizes, int n_in,
                              void* d_out, int out_size)
{
    (void)in_sizes; (void)n_in; (void)out_size;
    const float* x    = (const float*)d_in[0];
    const float* qw   = (const float*)d_in[1];
    const float* qb   = (const float*)d_in[2];
    const float* kw   = (const float*)d_in[3];
    const float* kb   = (const float*)d_in[4];
    const float* vw   = (const float*)d_in[5];
    const float* vb   = (const float*)d_in[6];
    const float* temp = (const float*)d_in[7];
    const float* lng  = (const float*)d_in[8];
    const float* lnb  = (const float*)d_in[9];
    const float* fw   = (const float*)d_in[10];
    const float* fb   = (const float*)d_in[11];
    float* out = (float*)d_out;

    float *q, *k, *v, *q2, *k2, *v2, *xr, *t1, *t2, *ln, *a1, *a2;
    cudaGetSymbolAddress((void**)&q,  g_q);
    cudaGetSymbolAddress((void**)&k,  g_k);
    cudaGetSymbolAddress((void**)&v,  g_v);
    cudaGetSymbolAddress((void**)&q2, g_q2);
    cudaGetSymbolAddress((void**)&k2, g_k2);
    cudaGetSymbolAddress((void**)&v2, g_v2);
    cudaGetSymbolAddress((void**)&xr, g_xr);
    cudaGetSymbolAddress((void**)&t1, g_t1);
    cudaGetSymbolAddress((void**)&t2, g_t2);
    cudaGetSymbolAddress((void**)&ln, g_ln);
    cudaGetSymbolAddress((void**)&a1, g_a1);
    cudaGetSymbolAddress((void**)&a2, g_a2);

    const int gemmSmem = 8 * GS * 2;                                   // 81920
    const int smem384  = (4*384*36 + 2*32*392 + 2*8*16*24) * 2 + 2*384*4;  // 176128
    const int smem128  = (4*128*36 + 2*32*136 + 2*8*16*24) * 2 + 2*128*4;  // 67584
    cudaFuncSetAttribute(gemm_tc, cudaFuncAttributeMaxDynamicSharedMemorySize, gemmSmem);
    cudaFuncSetAttribute(attn_tc, cudaFuncAttributeMaxDynamicSharedMemorySize, smem384);

    // Launch 1: all six QKV GEMMs (block0 full-T + blocks1-3 chunked)
    GArgs ga1;
    ga1.s[0] = { x, qw,       qb,       q,  0 };
    ga1.s[1] = { x, kw,       kb,       k,  0 };
    ga1.s[2] = { x, vw,       vb,       v,  0 };
    ga1.s[3] = { x, qw + WKN, qb + 512, q2, 1 };
    ga1.s[4] = { x, kw + WKN, kb + 512, k2, 1 };
    ga1.s[5] = { x, vw + WKN, vb + 512, v2, 1 };
    gemm_tc<<<dim3(4, 96, 6), 256, gemmSmem>>>(ga1);

    attn_tc<<<dim3(H_, 1, B_), 256, smem384>>>(q, k, v, temp, nullptr, xr, 384, 0);
    attn_tc<<<dim3(H_, 3, B_), 256, smem128>>>(q2, k2, v2, temp, xr, t1, 128, 1);

    ln_kernel<<<M_/8, 256>>>(t1, lng, lnb, ln);

    // Block 4 QKV on LN output
    GArgs ga2;
    ga2.s[0] = { ln, qw + 4*WKN, qb + 4*512, q, 0 };
    ga2.s[1] = { ln, kw + 4*WKN, kb + 4*512, k, 0 };
    ga2.s[2] = { ln, vw + 4*WKN, vb + 4*512, v, 0 };
    ga2.s[3] = ga2.s[0]; ga2.s[4] = ga2.s[0]; ga2.s[5] = ga2.s[0];
    gemm_tc<<<dim3(4, 96, 3), 256, gemmSmem>>>(ga2);

    attn_tc<<<dim3(H_, 1, B_), 256, smem384>>>(q, k, v, temp, xr, t2, 384, 4);

    // Fusion gating logits
    GArgs ga3;
    ga3.s[0] = { t1, fw, fb, a1, 0 };
    ga3.s[1] = { t2, fw, fb, a2, 0 };
    ga3.s[2] = ga3.s[0]; ga3.s[3] = ga3.s[0]; ga3.s[4] = ga3.s[0]; ga3.s[5] = ga3.s[0];
    gemm_tc<<<dim3(4, 96, 2), 256, gemmSmem>>>(ga3);

    fuse_kernel<<<BTD/4/256, 256>>>((const float4*)t1, (const float4*)t2,
                                    (const float4*)a1, (const float4*)a2, (float4*)out);
}

// round 6
// speedup vs baseline: 2.4315x; 1.0908x over previous
#include <cuda_runtime.h>
#include <cuda_fp16.h>
#include <math.h>
#include <stdint.h>

#define B_  32
#define T_  384
#define D_  512
#define H_  16
#define BTD (B_*T_*D_)     // 6291456
#define M_  (B_*T_)        // 12288
#define WKN (512*512)

// ---------------- scratch (static device globals; no cudaMalloc) ----------
__device__ float g_xr[BTD], g_t1[BTD], g_t2[BTD], g_a1[BTD], g_a2[BTD];
__device__ __half g_qh[BTD], g_ql[BTD], g_kh[BTD], g_kl[BTD], g_vh[BTD], g_vl[BTD];
__device__ __half g_q2h[BTD], g_q2l[BTD], g_k2h[BTD], g_k2l[BTD], g_v2h[BTD], g_v2l[BTD];
__device__ __half g_xh[BTD],  g_xl[BTD];
__device__ __half g_lnh[BTD], g_lnl[BTD];
__device__ __half g_t1h[BTD], g_t1l[BTD], g_t2h[BTD], g_t2l[BTD];
__device__ __half g_wh[16*WKN], g_wl[16*WKN];   // [qw0-4 | kw0-4 | vw0-4 | fw]

// ---------------- helpers --------------------------------------------------
__device__ __forceinline__ void split_h(float x, __half& hi, __half& lo) {
    hi = __float2half_rn(x);
    lo = __float2half_rn(x - __half2float(hi));
}
__device__ __forceinline__ unsigned pack2(__half a, __half b) {
    __half2 h = __halves2half2(a, b);
    return *reinterpret_cast<unsigned*>(&h);
}
__device__ __forceinline__ void mma_f16(float* c, const unsigned* a, unsigned b0, unsigned b1) {
    asm volatile("mma.sync.aligned.m16n8k16.row.col.f32.f16.f16.f32 "
        "{%0,%1,%2,%3}, {%4,%5,%6,%7}, {%8,%9}, {%0,%1,%2,%3};"
        : "+f"(c[0]), "+f"(c[1]), "+f"(c[2]), "+f"(c[3])
        : "r"(a[0]), "r"(a[1]), "r"(a[2]), "r"(a[3]), "r"(b0), "r"(b1));
}
__device__ __forceinline__ unsigned lduh2(const __half* p) {
    return *reinterpret_cast<const unsigned*>(p);
}
__device__ __forceinline__ uint32_t smem_u32(const void* p) {
    uint32_t a;
    asm("{ .reg .u64 t; cvta.to.shared.u64 t, %1; cvt.u32.u64 %0, t; }" : "=r"(a) : "l"(p));
    return a;
}
__device__ __forceinline__ void cpa16(uint32_t dst, const void* src) {
    asm volatile("cp.async.cg.shared.global [%0], [%1], 16;" :: "r"(dst), "l"(src) : "memory");
}

// ---------------------------------------------------------------------------
// fp16-split GEMM with cp.async 4-stage pipeline.
// C(M,512) = A(M,512) @ W(512,512)^T + bias. CTA tile 128x128, 8 warps
// (32m x 64n each), k-chunk 32 halves, pad rows to 40 halves (80B, multiple
// of 16 for cp.async, conflict-free LDS in the mma loop).
// Epilogue writes either fp32 C or split-fp16 (Chi, Clo).
// ---------------------------------------------------------------------------
#define ABYTES 10240          // one array, one stage: 128 rows * 80 B
struct G5 { const __half* Ah; const __half* Al; int wbase; int wadd;
            const float* bias; float* C; __half* Chi; __half* Clo; int chunk; };
struct G5Args { G5 s[6]; };

__global__ __launch_bounds__(256) void gemm_tc(G5Args ga)
{
    extern __shared__ __half smh[];
    const uint32_t sm32 = smem_u32(smh);
    const int tid = threadIdx.x, lane = tid & 31, wid = tid >> 5;
    const int wm = wid & 3, wn = wid >> 2, qr = lane >> 2, qc = lane & 3;

    const G5 sl = ga.s[blockIdx.z];
    const int m0 = blockIdx.y * 128, n0 = blockIdx.x * 128;
    const int widx = sl.chunk ? (1 + (m0 % 384) / 128) : sl.wadd;
    const __half* Wh = g_wh + (size_t)(sl.wbase + widx) * WKN;
    const __half* Wl = g_wl + (size_t)(sl.wbase + widx) * WKN;
    const float*  bp = sl.bias + widx * 512;

    // byte offsets of the 4 arrays (each 4 stages)
    // Ahi: 0, Alo: 40960, Whi: 81920, Wlo: 122880
    auto issue = [&](int c) {
        const int st = c & 3;
        const int kb = c * 32;          // halves
#pragma unroll
        for (int r = 0; r < 2; r++) {
            int e   = tid + r * 256;    // 0..511
            int row = e >> 2;           // 0..127
            int seg = e & 3;            // 16B segment in 64B row-chunk
            uint32_t d = sm32 + st * ABYTES + row * 80 + seg * 16;
            size_t gA = (size_t)(m0 + row) * 512 + kb + seg * 8;
            size_t gW = (size_t)(n0 + row) * 512 + kb + seg * 8;
            cpa16(d,          sl.Ah + gA);
            cpa16(d + 40960,  sl.Al + gA);
            cpa16(d + 81920,  Wh + gW);
            cpa16(d + 122880, Wl + gW);
        }
    };

    float acc[2][8][4];
#pragma unroll
    for (int mi = 0; mi < 2; mi++)
#pragma unroll
        for (int ni = 0; ni < 8; ni++)
#pragma unroll
            for (int j = 0; j < 4; j++) acc[mi][ni][j] = 0.f;

#pragma unroll
    for (int c = 0; c < 3; c++) {
        issue(c);
        asm volatile("cp.async.commit_group;" ::: "memory");
    }

    for (int c = 0; c < 16; c++) {
        asm volatile("cp.async.wait_group 2;" ::: "memory");
        __syncthreads();
        const int st = c & 3;
        const __half* Ah_s = smh + st * (ABYTES/2);
        const __half* Al_s = smh + (40960/2)  + st * (ABYTES/2);
        const __half* Wh_s = smh + (81920/2)  + st * (ABYTES/2);
        const __half* Wl_s = smh + (122880/2) + st * (ABYTES/2);
#pragma unroll
        for (int ks = 0; ks < 2; ks++) {
            const int kb = ks * 16 + 2 * qc;
            unsigned ah[2][4], al[2][4];
#pragma unroll
            for (int mi = 0; mi < 2; mi++) {
                int rb = wm * 32 + mi * 16;
                ah[mi][0] = lduh2(Ah_s + (rb+qr  )*40 + kb);
                ah[mi][1] = lduh2(Ah_s + (rb+qr+8)*40 + kb);
                ah[mi][2] = lduh2(Ah_s + (rb+qr  )*40 + kb + 8);
                ah[mi][3] = lduh2(Ah_s + (rb+qr+8)*40 + kb + 8);
                al[mi][0] = lduh2(Al_s + (rb+qr  )*40 + kb);
                al[mi][1] = lduh2(Al_s + (rb+qr+8)*40 + kb);
                al[mi][2] = lduh2(Al_s + (rb+qr  )*40 + kb + 8);
                al[mi][3] = lduh2(Al_s + (rb+qr+8)*40 + kb + 8);
            }
#pragma unroll
            for (int ni = 0; ni < 8; ni++) {
                int nr = wn * 64 + ni * 8 + qr;
                unsigned bh0 = lduh2(Wh_s + nr*40 + kb);
                unsigned bh1 = lduh2(Wh_s + nr*40 + kb + 8);
                unsigned bl0 = lduh2(Wl_s + nr*40 + kb);
                unsigned bl1 = lduh2(Wl_s + nr*40 + kb + 8);
#pragma unroll
                for (int mi = 0; mi < 2; mi++) {
                    mma_f16(acc[mi][ni], ah[mi], bh0, bh1);
                    mma_f16(acc[mi][ni], ah[mi], bl0, bl1);
                    mma_f16(acc[mi][ni], al[mi], bh0, bh1);
                }
            }
        }
        __syncthreads();
        if (c + 3 < 16) issue(c + 3);
        asm volatile("cp.async.commit_group;" ::: "memory");
    }

    // epilogue
#pragma unroll
    for (int mi = 0; mi < 2; mi++) {
#pragma unroll
        for (int ni = 0; ni < 8; ni++) {
            int row = m0 + wm * 32 + mi * 16 + qr;
            int col = n0 + wn * 64 + ni * 8 + 2 * qc;
            float2 bb = *(const float2*)(bp + col);
            float v00 = acc[mi][ni][0] + bb.x, v01 = acc[mi][ni][1] + bb.y;
            float v10 = acc[mi][ni][2] + bb.x, v11 = acc[mi][ni][3] + bb.y;
            if (sl.Chi) {
                __half h0,h1,l0,l1;
                split_h(v00,h0,l0); split_h(v01,h1,l1);
                *(unsigned*)(sl.Chi + (size_t)row*512 + col) = pack2(h0,h1);
                *(unsigned*)(sl.Clo + (size_t)row*512 + col) = pack2(l0,l1);
                split_h(v10,h0,l0); split_h(v11,h1,l1);
                *(unsigned*)(sl.Chi + (size_t)(row+8)*512 + col) = pack2(h0,h1);
                *(unsigned*)(sl.Clo + (size_t)(row+8)*512 + col) = pack2(l0,l1);
            } else {
                float2 o0 = { v00, v01 }, o1 = { v10, v11 };
                *(float2*)(sl.C + (size_t)row * 512 + col)       = o0;
                *(float2*)(sl.C + (size_t)(row + 8) * 512 + col) = o1;
            }
        }
    }
}

// ---------------------------------------------------------------------------
// split kernels: f32 -> (hi, lo) fp16 pairs
// ---------------------------------------------------------------------------
struct SpEnt { const float* src; __half* hi; __half* lo; int n; };
struct SpArgs { SpEnt e[5]; };

__global__ __launch_bounds__(256) void split_kernel(SpArgs sa)
{
    SpEnt E = sa.e[blockIdx.z];
    int stride = gridDim.x * 256;
    for (int i = blockIdx.x * 256 + threadIdx.x; i * 4 < E.n; i += stride) {
        float4 v = ((const float4*)E.src)[i];
        __half h0,h1,h2,h3,l0,l1,l2,l3;
        split_h(v.x,h0,l0); split_h(v.y,h1,l1); split_h(v.z,h2,l2); split_h(v.w,h3,l3);
        uint2 uh = { pack2(h0,h1), pack2(h2,h3) };
        uint2 ul = { pack2(l0,l1), pack2(l2,l3) };
        *(uint2*)(E.hi + 4*i) = uh;
        *(uint2*)(E.lo + 4*i) = ul;
    }
}

// ---------------------------------------------------------------------------
// fp16-split tensor-core attention; consumes pre-split half Q/K/V.
// ---------------------------------------------------------------------------
__global__ __launch_bounds__(256) void attn_tc(
    const __half* __restrict__ Qbh, const __half* __restrict__ Qbl,
    const __half* __restrict__ Kbh, const __half* __restrict__ Kbl,
    const __half* __restrict__ Vbh, const __half* __restrict__ Vbl,
    const float* __restrict__ temp,
    const float* __restrict__ addend, float* __restrict__ Ob,
    int T, int tempBase)
{
    extern __shared__ __half smh[];
    const int QS = T + 8;
    __half* Khi = smh;
    __half* Klo = Khi + T * 36;
    __half* Vhi = Klo + T * 36;
    __half* Vlo = Vhi + T * 36;
    __half* Qhi = Vlo + T * 36;
    __half* Qlo = Qhi + 32 * QS;
    float*  Mv  = (float*)(Qlo + 32 * QS);
    float*  Lv  = Mv + T;
    __half* Pshi = (__half*)(Lv + T);
    __half* Pslo = Pshi + 8 * 16 * 24;

    const int h = blockIdx.x, c = blockIdx.y, b = blockIdx.z;
    const int tid = threadIdx.x, lane = tid & 31, wid = tid >> 5;
    const int qr = lane >> 2, qc = lane & 3;
    const size_t off = (size_t)b * (T_*D_) + (size_t)c * (128*D_) + (size_t)h * 32 * T;
    const float scale = temp[(tempBase + c) * H_ + h];

    for (int idx = tid; idx < 32 * T; idx += 256) {
        int i = idx / T, t = idx - i * T;
        Khi[t*36 + i] = Kbh[off + idx];
        Klo[t*36 + i] = Kbl[off + idx];
        Vhi[t*36 + i] = Vbh[off + idx];
        Vlo[t*36 + i] = Vbl[off + idx];
        Qhi[i*QS + t] = Qbh[off + idx];
        Qlo[i*QS + t] = Qbl[off + idx];
    }
    __syncthreads();

    const int nb = T >> 4;

    // ---------------- Pass 1: row stats ----------------
    for (int tb = wid; tb < nb; tb += 8) {
        const int t0 = tb * 16;
        unsigned ah[2][4], al[2][4];
#pragma unroll
        for (int ks = 0; ks < 2; ks++) {
            const int kb = ks * 16 + 2 * qc;
            ah[ks][0] = lduh2(Khi + (t0+qr  )*36 + kb);
            ah[ks][1] = lduh2(Khi + (t0+qr+8)*36 + kb);
            ah[ks][2] = lduh2(Khi + (t0+qr  )*36 + kb + 8);
            ah[ks][3] = lduh2(Khi + (t0+qr+8)*36 + kb + 8);
            al[ks][0] = lduh2(Klo + (t0+qr  )*36 + kb);
            al[ks][1] = lduh2(Klo + (t0+qr+8)*36 + kb);
            al[ks][2] = lduh2(Klo + (t0+qr  )*36 + kb + 8);
            al[ks][3] = lduh2(Klo + (t0+qr+8)*36 + kb + 8);
        }
        float m0 = -3.0e38f, m1 = -3.0e38f, l0 = 0.f, l1 = 0.f;
        for (int s0 = 0; s0 < T; s0 += 64) {
            float cc[8][4];
#pragma unroll
            for (int nt = 0; nt < 8; nt++)
#pragma unroll
                for (int j = 0; j < 4; j++) cc[nt][j] = 0.f;
#pragma unroll
            for (int ks = 0; ks < 2; ks++) {
                const int kb = ks * 16 + 2 * qc;
#pragma unroll
                for (int nt = 0; nt < 8; nt++) {
                    int sr = s0 + nt * 8 + qr;
                    unsigned bh0 = lduh2(Vhi + sr*36 + kb);
                    unsigned bh1 = lduh2(Vhi + sr*36 + kb + 8);
                    unsigned bl0 = lduh2(Vlo + sr*36 + kb);
                    unsigned bl1 = lduh2(Vlo + sr*36 + kb + 8);
                    mma_f16(cc[nt], ah[ks], bh0, bh1);
                    mma_f16(cc[nt], ah[ks], bl0, bl1);
                    mma_f16(cc[nt], al[ks], bh0, bh1);
                }
            }
            float cm0 = -3.0e38f, cm1 = -3.0e38f;
#pragma unroll
            for (int nt = 0; nt < 8; nt++) {
#pragma unroll
                for (int j = 0; j < 4; j++) cc[nt][j] *= scale;
                cm0 = fmaxf(cm0, fmaxf(cc[nt][0], cc[nt][1]));
                cm1 = fmaxf(cm1, fmaxf(cc[nt][2], cc[nt][3]));
            }
            cm0 = fmaxf(cm0, __shfl_xor_sync(0xffffffffu, cm0, 1));
            cm0 = fmaxf(cm0, __shfl_xor_sync(0xffffffffu, cm0, 2));
            cm1 = fmaxf(cm1, __shfl_xor_sync(0xffffffffu, cm1, 1));
            cm1 = fmaxf(cm1, __shfl_xor_sync(0xffffffffu, cm1, 2));
            float M0 = fmaxf(m0, cm0), M1 = fmaxf(m1, cm1);
            float p0 = 0.f, p1 = 0.f;
#pragma unroll
            for (int nt = 0; nt < 8; nt++) {
                p0 += __expf(cc[nt][0] - M0) + __expf(cc[nt][1] - M0);
                p1 += __expf(cc[nt][2] - M1) + __expf(cc[nt][3] - M1);
            }
            p0 += __shfl_xor_sync(0xffffffffu, p0, 1);
            p0 += __shfl_xor_sync(0xffffffffu, p0, 2);
            p1 += __shfl_xor_sync(0xffffffffu, p1, 1);
            p1 += __shfl_xor_sync(0xffffffffu, p1, 2);
            l0 = l0 * __expf(m0 - M0) + p0;  m0 = M0;
            l1 = l1 * __expf(m1 - M1) + p1;  m1 = M1;
        }
        if (qc == 0) {
            Mv[t0 + qr]     = m0;  Lv[t0 + qr]     = 1.f / l0;
            Mv[t0 + qr + 8] = m1;  Lv[t0 + qr + 8] = 1.f / l1;
        }
    }
    __syncthreads();

    // ---------------- Pass 2: output ----------------
    __half* Pwh = Pshi + wid * (16 * 24);
    __half* Pwl = Pslo + wid * (16 * 24);
    for (int sb = wid; sb < nb; sb += 8) {
        const int s0 = sb * 16;
        unsigned vh[2][4], vl[2][4];
#pragma unroll
        for (int ks = 0; ks < 2; ks++) {
            const int kb = ks * 16 + 2 * qc;
            vh[ks][0] = lduh2(Vhi + (s0+qr  )*36 + kb);
            vh[ks][1] = lduh2(Vhi + (s0+qr+8)*36 + kb);
            vh[ks][2] = lduh2(Vhi + (s0+qr  )*36 + kb + 8);
            vh[ks][3] = lduh2(Vhi + (s0+qr+8)*36 + kb + 8);
            vl[ks][0] = lduh2(Vlo + (s0+qr  )*36 + kb);
            vl[ks][1] = lduh2(Vlo + (s0+qr+8)*36 + kb);
            vl[ks][2] = lduh2(Vlo + (s0+qr  )*36 + kb + 8);
            vl[ks][3] = lduh2(Vlo + (s0+qr+8)*36 + kb + 8);
        }
        float o[4][4];
#pragma unroll
        for (int ni = 0; ni < 4; ni++)
#pragma unroll
            for (int j = 0; j < 4; j++) o[ni][j] = 0.f;

        for (int t0 = 0; t0 < T; t0 += 16) {
            float e[2][4];
#pragma unroll
            for (int nt = 0; nt < 2; nt++)
#pragma unroll
                for (int j = 0; j < 4; j++) e[nt][j] = 0.f;
#pragma unroll
            for (int ks = 0; ks < 2; ks++) {
                const int kb = ks * 16 + 2 * qc;
#pragma unroll
                for (int nt = 0; nt < 2; nt++) {
                    int tr = t0 + nt * 8 + qr;
                    unsigned bh0 = lduh2(Khi + tr*36 + kb);
                    unsigned bh1 = lduh2(Khi + tr*36 + kb + 8);
                    unsigned bl0 = lduh2(Klo + tr*36 + kb);
                    unsigned bl1 = lduh2(Klo + tr*36 + kb + 8);
                    mma_f16(e[nt], vh[ks], bh0, bh1);
                    mma_f16(e[nt], vh[ks], bl0, bl1);
                    mma_f16(e[nt], vl[ks], bh0, bh1);
                }
            }
            __syncwarp();
#pragma unroll
            for (int nt = 0; nt < 2; nt++) {
                int tc = t0 + nt * 8 + 2 * qc;
                float mva = Mv[tc],   lva = Lv[tc];
                float mvb = Mv[tc+1], lvb = Lv[tc+1];
                float e0 = __expf(e[nt][0] * scale - mva) * lva;
                float e1 = __expf(e[nt][1] * scale - mvb) * lvb;
                float e2 = __expf(e[nt][2] * scale - mva) * lva;
                float e3 = __expf(e[nt][3] * scale - mvb) * lvb;
                __half h0, h1, h2, h3, g0, g1, g2, g3;
                split_h(e0, h0, g0); split_h(e1, h1, g1);
                split_h(e2, h2, g2); split_h(e3, h3, g3);
                *(unsigned*)(Pwh + qr*24     + nt*8 + 2*qc) = pack2(h0, h1);
                *(unsigned*)(Pwh + (qr+8)*24 + nt*8 + 2*qc) = pack2(h2, h3);
                *(unsigned*)(Pwl + qr*24     + nt*8 + 2*qc) = pack2(g0, g1);
                *(unsigned*)(Pwl + (qr+8)*24 + nt*8 + 2*qc) = pack2(g2, g3);
            }
            __syncwarp();
            unsigned ph[4], pl[4];
            ph[0] = lduh2(Pwh + qr*24     + 2*qc);
            ph[1] = lduh2(Pwh + (qr+8)*24 + 2*qc);
            ph[2] = lduh2(Pwh + qr*24     + 2*qc + 8);
            ph[3] = lduh2(Pwh + (qr+8)*24 + 2*qc + 8);
            pl[0] = lduh2(Pwl + qr*24     + 2*qc);
            pl[1] = lduh2(Pwl + (qr+8)*24 + 2*qc);
            pl[2] = lduh2(Pwl + qr*24     + 2*qc + 8);
            pl[3] = lduh2(Pwl + (qr+8)*24 + 2*qc + 8);
#pragma unroll
            for (int ni = 0; ni < 4; ni++) {
                int ir = ni * 8 + qr;
                unsigned qb0 = lduh2(Qhi + ir*QS + t0 + 2*qc);
                unsigned qb1 = lduh2(Qhi + ir*QS + t0 + 2*qc + 8);
                unsigned ql0 = lduh2(Qlo + ir*QS + t0 + 2*qc);
                unsigned ql1 = lduh2(Qlo + ir*QS + t0 + 2*qc + 8);
                mma_f16(o[ni], ph, qb0, qb1);
                mma_f16(o[ni], ph, ql0, ql1);
                mma_f16(o[ni], pl, qb0, qb1);
            }
        }
#pragma unroll
        for (int ni = 0; ni < 4; ni++) {
            int icol = ni * 8 + 2 * qc;
            int srow = s0 + qr;
            size_t base = off + (size_t)icol * T + srow;
            if (addend != nullptr) {
                Ob[base]         = o[ni][0] + addend[base];
                Ob[base + T]     = o[ni][1] + addend[base + T];
                Ob[base + 8]     = o[ni][2] + addend[base + 8];
                Ob[base + T + 8] = o[ni][3] + addend[base + T + 8];
            } else {
                Ob[base]         = o[ni][0];
                Ob[base + T]     = o[ni][1];
                Ob[base + 8]     = o[ni][2];
                Ob[base + T + 8] = o[ni][3];
            }
        }
    }
}

// ---------------------------------------------------------------------------
// LayerNorm: one warp per 512-wide row; emits split fp16 directly.
// ---------------------------------------------------------------------------
__global__ __launch_bounds__(256) void ln_kernel(
    const float* __restrict__ X, const float* __restrict__ gw,
    const float* __restrict__ gb, __half* __restrict__ Yh, __half* __restrict__ Yl)
{
    const int row  = blockIdx.x * 8 + (threadIdx.x >> 5);
    const int lane = threadIdx.x & 31;
    const float4* xr = (const float4*)(X + (size_t)row * D_);
    float4 v[4];
    float s = 0.f, ss = 0.f;
#pragma unroll
    for (int w = 0; w < 4; w++) {
        v[w] = xr[w*32 + lane];
        s  += v[w].x + v[w].y + v[w].z + v[w].w;
        ss += v[w].x*v[w].x + v[w].y*v[w].y + v[w].z*v[w].z + v[w].w*v[w].w;
    }
#pragma unroll
    for (int o = 16; o > 0; o >>= 1) {
        s  += __shfl_xor_sync(0xffffffffu, s, o);
        ss += __shfl_xor_sync(0xffffffffu, ss, o);
    }
    const float mean = s * (1.f/512.f);
    const float var  = ss * (1.f/512.f) - mean*mean;
    const float r = rsqrtf(var + 1e-5f);
    const float4* gr = (const float4*)gw;
    const float4* br = (const float4*)gb;
#pragma unroll
    for (int w = 0; w < 4; w++) {
        float4 gv = gr[w*32 + lane];
        float4 bv = br[w*32 + lane];
        float o0 = (v[w].x - mean) * r * gv.x + bv.x;
        float o1 = (v[w].y - mean) * r * gv.y + bv.y;
        float o2 = (v[w].z - mean) * r * gv.z + bv.z;
        float o3 = (v[w].w - mean) * r * gv.w + bv.w;
        __half h0,h1,h2,h3,l0,l1,l2,l3;
        split_h(o0,h0,l0); split_h(o1,h1,l1); split_h(o2,h2,l2); split_h(o3,h3,l3);
        size_t idx = (size_t)row * D_ + (w*32 + lane) * 4;
        *(uint2*)(Yh + idx) = make_uint2(pack2(h0,h1), pack2(h2,h3));
        *(uint2*)(Yl + idx) = make_uint2(pack2(l0,l1), pack2(l2,l3));
    }
}

// ---------------------------------------------------------------------------
// Fusion gating
// ---------------------------------------------------------------------------
__device__ __forceinline__ float fuse1(float x1, float x2, float y1, float y2) {
    float mx = fmaxf(y1, y2);
    float e1 = __expf(y1 - mx), e2 = __expf(y2 - mx);
    return (x1*e1 + x2*e2) / (e1 + e2);
}

__global__ __launch_bounds__(256) void fuse_kernel(
    const float4* __restrict__ t1, const float4* __restrict__ t2,
    const float4* __restrict__ a1, const float4* __restrict__ a2,
    float4* __restrict__ out)
{
    int i = blockIdx.x * 256 + threadIdx.x;
    float4 x1 = t1[i], x2 = t2[i], y1 = a1[i], y2 = a2[i];
    float4 o;
    o.x = fuse1(x1.x, x2.x, y1.x, y2.x);
    o.y = fuse1(x1.y, x2.y, y1.y, y2.y);
    o.z = fuse1(x1.z, x2.z, y1.z, y2.z);
    o.w = fuse1(x1.w, x2.w, y1.w, y2.w);
    out[i] = o;
}

// ---------------------------------------------------------------------------
extern "C" void kernel_launch(void* const* d_in, const int* in_sizes, int n_in,
                              void* d_out, int out_size)
{
    (void)in_sizes; (void)n_in; (void)out_size;
    const float* x    = (const float*)d_in[0];
    const float* qw   = (const float*)d_in[1];
    const float* qb   = (const float*)d_in[2];
    const float* kw   = (const float*)d_in[3];
    const float* kb   = (const float*)d_in[4];
    const float* vw   = (const float*)d_in[5];
    const float* vb   = (const float*)d_in[6];
    const float* temp = (const float*)d_in[7];
    const float* lng  = (const float*)d_in[8];
    const float* lnb  = (const float*)d_in[9];
    const float* fw   = (const float*)d_in[10];
    const float* fb   = (const float*)d_in[11];
    float* out = (float*)d_out;

    float *xr, *t1, *t2, *a1, *a2;
    __half *qh,*ql,*kh2,*kl2,*vh2,*vl2, *q2h,*q2l,*k2h,*k2l,*v2h,*v2l;
    __half *xh, *xl, *lnh, *lnl, *t1h, *t1l, *t2h, *t2l, *wh, *wl;
    cudaGetSymbolAddress((void**)&xr, g_xr);
    cudaGetSymbolAddress((void**)&t1, g_t1);
    cudaGetSymbolAddress((void**)&t2, g_t2);
    cudaGetSymbolAddress((void**)&a1, g_a1);
    cudaGetSymbolAddress((void**)&a2, g_a2);
    cudaGetSymbolAddress((void**)&qh, g_qh);   cudaGetSymbolAddress((void**)&ql, g_ql);
    cudaGetSymbolAddress((void**)&kh2, g_kh);  cudaGetSymbolAddress((void**)&kl2, g_kl);
    cudaGetSymbolAddress((void**)&vh2, g_vh);  cudaGetSymbolAddress((void**)&vl2, g_vl);
    cudaGetSymbolAddress((void**)&q2h, g_q2h); cudaGetSymbolAddress((void**)&q2l, g_q2l);
    cudaGetSymbolAddress((void**)&k2h, g_k2h); cudaGetSymbolAddress((void**)&k2l, g_k2l);
    cudaGetSymbolAddress((void**)&v2h, g_v2h); cudaGetSymbolAddress((void**)&v2l, g_v2l);
    cudaGetSymbolAddress((void**)&xh, g_xh);   cudaGetSymbolAddress((void**)&xl, g_xl);
    cudaGetSymbolAddress((void**)&lnh, g_lnh); cudaGetSymbolAddress((void**)&lnl, g_lnl);
    cudaGetSymbolAddress((void**)&t1h, g_t1h); cudaGetSymbolAddress((void**)&t1l, g_t1l);
    cudaGetSymbolAddress((void**)&t2h, g_t2h); cudaGetSymbolAddress((void**)&t2l, g_t2l);
    cudaGetSymbolAddress((void**)&wh, g_wh);   cudaGetSymbolAddress((void**)&wl, g_wl);

    const int gemmSmem = 16 * ABYTES;                                      // 163840
    const int smem384  = (4*384*36 + 2*32*392 + 2*8*16*24) * 2 + 2*384*4;  // 176128
    const int smem128  = (4*128*36 + 2*32*136 + 2*8*16*24) * 2 + 2*128*4;
    cudaFuncSetAttribute(gemm_tc, cudaFuncAttributeMaxDynamicSharedMemorySize, gemmSmem);
    cudaFuncSetAttribute(attn_tc, cudaFuncAttributeMaxDynamicSharedMemorySize, smem384);

    // 1) pre-split x and all weight matrices
    SpArgs sp1;
    sp1.e[0] = { x,  xh,          xl,          BTD    };
    sp1.e[1] = { qw, wh + 0,      wl + 0,      5*WKN  };
    sp1.e[2] = { kw, wh + (size_t)5*WKN,  wl + (size_t)5*WKN,  5*WKN  };
    sp1.e[3] = { vw, wh + (size_t)10*WKN, wl + (size_t)10*WKN, 5*WKN  };
    sp1.e[4] = { fw, wh + (size_t)15*WKN, wl + (size_t)15*WKN, WKN    };
    split_kernel<<<dim3(512, 1, 5), 256>>>(sp1);

    // 2) QKV GEMMs (block0 full-T + blocks1-3 chunked), epilogue -> split halves
    G5Args ga1;
    ga1.s[0] = { xh, xl, 0,  0, qb, nullptr, qh,  ql,  0 };
    ga1.s[1] = { xh, xl, 5,  0, kb, nullptr, kh2, kl2, 0 };
    ga1.s[2] = { xh, xl, 10, 0, vb, nullptr, vh2, vl2, 0 };
    ga1.s[3] = { xh, xl, 0,  0, qb, nullptr, q2h, q2l, 1 };
    ga1.s[4] = { xh, xl, 5,  0, kb, nullptr, k2h, k2l, 1 };
    ga1.s[5] = { xh, xl, 10, 0, vb, nullptr, v2h, v2l, 1 };
    gemm_tc<<<dim3(4, 96, 6), 256, gemmSmem>>>(ga1);

    attn_tc<<<dim3(H_, 1, B_), 256, smem384>>>(qh, ql, kh2, kl2, vh2, vl2, temp, nullptr, xr, 384, 0);
    attn_tc<<<dim3(H_, 3, B_), 256, smem128>>>(q2h, q2l, k2h, k2l, v2h, v2l, temp, xr, t1, 128, 1);

    // 3) LayerNorm(t1) -> split fp16
    ln_kernel<<<M_/8, 256>>>(t1, lng, lnb, lnh, lnl);

    // 4) block4 QKV on LN output (reuse q/k/v half buffers)
    G5Args ga2;
    ga2.s[0] = { lnh, lnl, 0,  4, qb, nullptr, qh,  ql,  0 };
    ga2.s[1] = { lnh, lnl, 5,  4, kb, nullptr, kh2, kl2, 0 };
    ga2.s[2] = { lnh, lnl, 10, 4, vb, nullptr, vh2, vl2, 0 };
    ga2.s[3] = ga2.s[0]; ga2.s[4] = ga2.s[0]; ga2.s[5] = ga2.s[0];
    gemm_tc<<<dim3(4, 96, 3), 256, gemmSmem>>>(ga2);

    attn_tc<<<dim3(H_, 1, B_), 256, smem384>>>(qh, ql, kh2, kl2, vh2, vl2, temp, xr, t2, 384, 4);

    // 5) split t1, t2 for fusion GEMMs
    SpArgs sp2;
    sp2.e[0] = { t1, t1h, t1l, BTD };
    sp2.e[1] = { t2, t2h, t2l, BTD };
    sp2.e[2] = sp2.e[0]; sp2.e[3] = sp2.e[0]; sp2.e[4] = sp2.e[0];
    split_kernel<<<dim3(512, 1, 2), 256>>>(sp2);

    // 6) fusion gating logits (fp32 out) + combine
    G5Args ga3;
    ga3.s[0] = { t1h, t1l, 15, 0, fb, a1, nullptr, nullptr, 0 };
    ga3.s[1] = { t2h, t2l, 15, 0, fb, a2, nullptr, nullptr, 0 };
    ga3.s[2] = ga3.s[0]; ga3.s[3] = ga3.s[0]; ga3.s[4] = ga3.s[0]; ga3.s[5] = ga3.s[0];
    gemm_tc<<<dim3(4, 96, 2), 256, gemmSmem>>>(ga3);

    fuse_kernel<<<BTD/4/256, 256>>>((const float4*)t1, (const float4*)t2,
                                    (const float4*)a1, (const float4*)a2, (float4*)out);
}

// round 7
// speedup vs baseline: 2.6383x; 1.0851x over previous
#include <cuda_runtime.h>
#include <cuda_fp16.h>
#include <math.h>
#include <stdint.h>

#define B_  32
#define T_  384
#define D_  512
#define H_  16
#define BTD (B_*T_*D_)     // 6291456
#define M_  (B_*T_)        // 12288
#define WKN (512*512)

// ---------------- scratch (static device globals; no cudaMalloc) ----------
__device__ float g_xr[BTD], g_t1[BTD], g_t2[BTD], g_a1[BTD];
__device__ __half g_qh[BTD], g_ql[BTD], g_kh[BTD], g_kl[BTD], g_vh[BTD], g_vl[BTD];
__device__ __half g_q2h[BTD], g_q2l[BTD], g_k2h[BTD], g_k2l[BTD], g_v2h[BTD], g_v2l[BTD];
__device__ __half g_xh[BTD],  g_xl[BTD];
__device__ __half g_lnh[BTD], g_lnl[BTD];
__device__ __half g_dh[BTD],  g_dl[BTD];
__device__ __half g_wh[16*WKN], g_wl[16*WKN];   // [qw0-4 | kw0-4 | vw0-4 | fw]

// ---------------- helpers --------------------------------------------------
__device__ __forceinline__ void split_h(float x, __half& hi, __half& lo) {
    hi = __float2half_rn(x);
    lo = __float2half_rn(x - __half2float(hi));
}
__device__ __forceinline__ unsigned pack2(__half a, __half b) {
    __half2 h = __halves2half2(a, b);
    return *reinterpret_cast<unsigned*>(&h);
}
__device__ __forceinline__ void mma_f16(float* c, const unsigned* a, unsigned b0, unsigned b1) {
    asm volatile("mma.sync.aligned.m16n8k16.row.col.f32.f16.f16.f32 "
        "{%0,%1,%2,%3}, {%4,%5,%6,%7}, {%8,%9}, {%0,%1,%2,%3};"
        : "+f"(c[0]), "+f"(c[1]), "+f"(c[2]), "+f"(c[3])
        : "r"(a[0]), "r"(a[1]), "r"(a[2]), "r"(a[3]), "r"(b0), "r"(b1));
}
__device__ __forceinline__ void ldsm4(unsigned* r, uint32_t addr) {
    asm volatile("ldmatrix.sync.aligned.m8n8.x4.shared.b16 {%0,%1,%2,%3}, [%4];"
        : "=r"(r[0]), "=r"(r[1]), "=r"(r[2]), "=r"(r[3]) : "r"(addr));
}
__device__ __forceinline__ uint32_t smem_u32(const void* p) {
    uint32_t a;
    asm("{ .reg .u64 t; cvta.to.shared.u64 t, %1; cvt.u32.u64 %0, t; }" : "=r"(a) : "l"(p));
    return a;
}
__device__ __forceinline__ void cpa16(uint32_t dst, const void* src) {
    asm volatile("cp.async.cg.shared.global [%0], [%1], 16;" :: "r"(dst), "l"(src) : "memory");
}

// ---------------------------------------------------------------------------
// fp16-split GEMM, cp.async 4-stage pipeline + ldmatrix operand loads.
// C(M,512) = A(M,512) @ W(512,512)^T + bias. CTA 128x128, 8 warps (32x64),
// k-chunk 32 halves, rows padded to 40 halves (80B: 16B-multiple, LDSM
// conflict-free). split=1: 3-mma hi/lo; split=0: single fp16 (hi only).
// ---------------------------------------------------------------------------
#define ABYTES 10240          // one array, one stage: 128 rows * 80 B
struct G5 { const __half* Ah; const __half* Al; int wbase; int wadd;
            const float* bias; float* C; __half* Chi; __half* Clo;
            int chunk; int split; };
struct G5Args { G5 s[6]; };

__global__ __launch_bounds__(256) void gemm_tc(G5Args ga)
{
    extern __shared__ __half smh[];
    const uint32_t sm32 = smem_u32(smh);
    const int tid = threadIdx.x, lane = tid & 31, wid = tid >> 5;
    const int wm = wid & 3, wn = wid >> 2, qr = lane >> 2, qc = lane & 3;
    const uint32_t ro = (lane & 7) + ((lane >> 3) & 1) * 8;
    const uint32_t co = (lane >> 4) * 8;

    const G5 sl = ga.s[blockIdx.z];
    const int m0 = blockIdx.y * 128, n0 = blockIdx.x * 128;
    const int widx = sl.chunk ? (1 + (m0 % 384) / 128) : sl.wadd;
    const __half* Wh = g_wh + (size_t)(sl.wbase + widx) * WKN;
    const __half* Wl = g_wl + (size_t)(sl.wbase + widx) * WKN;
    const float*  bp = sl.bias ? sl.bias + widx * 512 : nullptr;
    const int split = sl.split;

    // arrays: Ahi @0, Alo @40960, Whi @81920, Wlo @122880 (4 stages each)
    auto issue = [&](int c) {
        const int st = c & 3;
        const int kb = c * 32;
#pragma unroll
        for (int r = 0; r < 2; r++) {
            int e   = tid + r * 256;
            int row = e >> 2;
            int seg = e & 3;
            uint32_t d = sm32 + st * ABYTES + row * 80 + seg * 16;
            size_t gA = (size_t)(m0 + row) * 512 + kb + seg * 8;
            size_t gW = (size_t)(n0 + row) * 512 + kb + seg * 8;
            cpa16(d,          sl.Ah + gA);
            cpa16(d + 81920,  Wh + gW);
            if (split) {
                cpa16(d + 40960,  sl.Al + gA);
                cpa16(d + 122880, Wl + gW);
            }
        }
    };

    float acc[2][8][4];
#pragma unroll
    for (int mi = 0; mi < 2; mi++)
#pragma unroll
        for (int ni = 0; ni < 8; ni++)
#pragma unroll
            for (int j = 0; j < 4; j++) acc[mi][ni][j] = 0.f;

#pragma unroll
    for (int c = 0; c < 3; c++) {
        issue(c);
        asm volatile("cp.async.commit_group;" ::: "memory");
    }

    for (int c = 0; c < 16; c++) {
        asm volatile("cp.async.wait_group 2;" ::: "memory");
        __syncthreads();
        const uint32_t sA = sm32 + (c & 3) * ABYTES;
#pragma unroll
        for (int ks = 0; ks < 2; ks++) {
            unsigned ah[2][4], al[2][4];
#pragma unroll
            for (int mi = 0; mi < 2; mi++) {
                uint32_t ra = sA + ((wm*32 + mi*16 + ro) * 40 + ks*16 + co) * 2;
                ldsm4(ah[mi], ra);
                if (split) ldsm4(al[mi], ra + 40960);
            }
#pragma unroll
            for (int p = 0; p < 4; p++) {
                uint32_t rw = sA + 81920 + ((wn*64 + p*16 + ro) * 40 + ks*16 + co) * 2;
                unsigned wh4[4], wl4[4];
                ldsm4(wh4, rw);
                if (split) ldsm4(wl4, rw + 40960);
#pragma unroll
                for (int mi = 0; mi < 2; mi++) {
                    mma_f16(acc[mi][2*p],   ah[mi], wh4[0], wh4[2]);
                    mma_f16(acc[mi][2*p+1], ah[mi], wh4[1], wh4[3]);
                    if (split) {
                        mma_f16(acc[mi][2*p],   ah[mi], wl4[0], wl4[2]);
                        mma_f16(acc[mi][2*p],   al[mi], wh4[0], wh4[2]);
                        mma_f16(acc[mi][2*p+1], ah[mi], wl4[1], wl4[3]);
                        mma_f16(acc[mi][2*p+1], al[mi], wh4[1], wh4[3]);
                    }
                }
            }
        }
        if (c + 3 < 16) issue(c + 3);
        asm volatile("cp.async.commit_group;" ::: "memory");
    }

    // epilogue
#pragma unroll
    for (int mi = 0; mi < 2; mi++) {
#pragma unroll
        for (int ni = 0; ni < 8; ni++) {
            int row = m0 + wm * 32 + mi * 16 + qr;
            int col = n0 + wn * 64 + ni * 8 + 2 * qc;
            float bx = 0.f, by = 0.f;
            if (bp) { float2 bb = *(const float2*)(bp + col); bx = bb.x; by = bb.y; }
            float v00 = acc[mi][ni][0] + bx, v01 = acc[mi][ni][1] + by;
            float v10 = acc[mi][ni][2] + bx, v11 = acc[mi][ni][3] + by;
            if (sl.Chi) {
                __half h0,h1,l0,l1;
                split_h(v00,h0,l0); split_h(v01,h1,l1);
                *(unsigned*)(sl.Chi + (size_t)row*512 + col) = pack2(h0,h1);
                *(unsigned*)(sl.Clo + (size_t)row*512 + col) = pack2(l0,l1);
                split_h(v10,h0,l0); split_h(v11,h1,l1);
                *(unsigned*)(sl.Chi + (size_t)(row+8)*512 + col) = pack2(h0,h1);
                *(unsigned*)(sl.Clo + (size_t)(row+8)*512 + col) = pack2(l0,l1);
            } else {
                float2 o0 = { v00, v01 }, o1 = { v10, v11 };
                *(float2*)(sl.C + (size_t)row * 512 + col)       = o0;
                *(float2*)(sl.C + (size_t)(row + 8) * 512 + col) = o1;
            }
        }
    }
}

// ---------------------------------------------------------------------------
// split kernels: f32 -> (hi, lo) fp16 pairs
// ---------------------------------------------------------------------------
struct SpEnt { const float* src; __half* hi; __half* lo; int n; };
struct SpArgs { SpEnt e[5]; };

__global__ __launch_bounds__(256) void split_kernel(SpArgs sa)
{
    SpEnt E = sa.e[blockIdx.z];
    int stride = gridDim.x * 256;
    for (int i = blockIdx.x * 256 + threadIdx.x; i * 4 < E.n; i += stride) {
        float4 v = ((const float4*)E.src)[i];
        __half h0,h1,h2,h3,l0,l1,l2,l3;
        split_h(v.x,h0,l0); split_h(v.y,h1,l1); split_h(v.z,h2,l2); split_h(v.w,h3,l3);
        *(uint2*)(E.hi + 4*i) = make_uint2(pack2(h0,h1), pack2(h2,h3));
        *(uint2*)(E.lo + 4*i) = make_uint2(pack2(l0,l1), pack2(l2,l3));
    }
}

// diff+split: d = t1 - t2 -> (hi, lo)
__global__ __launch_bounds__(256) void diff_split_kernel(
    const float4* __restrict__ t1, const float4* __restrict__ t2,
    __half* __restrict__ hi, __half* __restrict__ lo)
{
    int i = blockIdx.x * 256 + threadIdx.x;
    float4 a = t1[i], b = t2[i];
    __half h0,h1,h2,h3,l0,l1,l2,l3;
    split_h(a.x-b.x,h0,l0); split_h(a.y-b.y,h1,l1);
    split_h(a.z-b.z,h2,l2); split_h(a.w-b.w,h3,l3);
    *(uint2*)(hi + 4*i) = make_uint2(pack2(h0,h1), pack2(h2,h3));
    *(uint2*)(lo + 4*i) = make_uint2(pack2(l0,l1), pack2(l2,l3));
}

// ---------------------------------------------------------------------------
// fp16-split attention with ldmatrix operand loads. K/V tiles [T][40],
// Q [32][QS] (QS = T+8; stride bytes multiple of 16). One CTA/(b,h[,chunk]).
// ---------------------------------------------------------------------------
__global__ __launch_bounds__(256) void attn_tc(
    const __half* __restrict__ Qbh, const __half* __restrict__ Qbl,
    const __half* __restrict__ Kbh, const __half* __restrict__ Kbl,
    const __half* __restrict__ Vbh, const __half* __restrict__ Vbl,
    const float* __restrict__ temp,
    const float* __restrict__ addend, float* __restrict__ Ob,
    int T, int tempBase)
{
    extern __shared__ __half smh[];
    const int QS = T + 8;
    __half* Khi = smh;                       // [T][40]
    __half* Klo = Khi + T * 40;
    __half* Vhi = Klo + T * 40;
    __half* Vlo = Vhi + T * 40;
    __half* Qhi = Vlo + T * 40;              // [32][QS]
    __half* Qlo = Qhi + 32 * QS;
    float*  Mv  = (float*)(Qlo + 32 * QS);
    float*  Lv  = Mv + T;
    __half* Pshi = (__half*)(Lv + T);        // 8 warps * [16][24]
    __half* Pslo = Pshi + 8 * 16 * 24;

    const uint32_t smA   = smem_u32(smh);
    const uint32_t KVoff = (uint32_t)T * 80;     // hi->lo byte distance (K,V)
    const uint32_t Qoff  = (uint32_t)32 * QS * 2;

    const int h = blockIdx.x, c = blockIdx.y, b = blockIdx.z;
    const int tid = threadIdx.x, lane = tid & 31, wid = tid >> 5;
    const int qr = lane >> 2, qc = lane & 3;
    const uint32_t ro = (lane & 7) + ((lane >> 3) & 1) * 8;
    const uint32_t co = (lane >> 4) * 8;
    const size_t off = (size_t)b * (T_*D_) + (size_t)c * (128*D_) + (size_t)h * 32 * T;
    const float scale = temp[(tempBase + c) * H_ + h];

    for (int idx = tid; idx < 32 * T; idx += 256) {
        int i = idx / T, t = idx - i * T;
        Khi[t*40 + i] = Kbh[off + idx];
        Klo[t*40 + i] = Kbl[off + idx];
        Vhi[t*40 + i] = Vbh[off + idx];
        Vlo[t*40 + i] = Vbl[off + idx];
        Qhi[i*QS + t] = Qbh[off + idx];
        Qlo[i*QS + t] = Qbl[off + idx];
    }
    __syncthreads();

    const int nb = T >> 4;
    const uint32_t KhiA = smA;
    const uint32_t VhiA = smA + 2 * KVoff;
    const uint32_t QhiA = smA + 4 * KVoff;

    // ---------------- Pass 1: row stats ----------------
    for (int tb = wid; tb < nb; tb += 8) {
        const int t0 = tb * 16;
        unsigned ah[2][4], al[2][4];
#pragma unroll
        for (int ks = 0; ks < 2; ks++) {
            uint32_t ra = KhiA + (((uint32_t)t0 + ro) * 40 + ks*16 + co) * 2;
            ldsm4(ah[ks], ra);
            ldsm4(al[ks], ra + KVoff);
        }
        float m0 = -3.0e38f, m1 = -3.0e38f, l0 = 0.f, l1 = 0.f;
        for (int s0 = 0; s0 < T; s0 += 64) {
            float cc[8][4];
#pragma unroll
            for (int nt = 0; nt < 8; nt++)
#pragma unroll
                for (int j = 0; j < 4; j++) cc[nt][j] = 0.f;
#pragma unroll
            for (int ks = 0; ks < 2; ks++) {
#pragma unroll
                for (int p = 0; p < 4; p++) {
                    uint32_t rv = VhiA + (((uint32_t)(s0 + p*16) + ro) * 40 + ks*16 + co) * 2;
                    unsigned vh4[4], vl4[4];
                    ldsm4(vh4, rv);
                    ldsm4(vl4, rv + KVoff);
                    mma_f16(cc[2*p],   ah[ks], vh4[0], vh4[2]);
                    mma_f16(cc[2*p],   ah[ks], vl4[0], vl4[2]);
                    mma_f16(cc[2*p],   al[ks], vh4[0], vh4[2]);
                    mma_f16(cc[2*p+1], ah[ks], vh4[1], vh4[3]);
                    mma_f16(cc[2*p+1], ah[ks], vl4[1], vl4[3]);
                    mma_f16(cc[2*p+1], al[ks], vh4[1], vh4[3]);
                }
            }
            float cm0 = -3.0e38f, cm1 = -3.0e38f;
#pragma unroll
            for (int nt = 0; nt < 8; nt++) {
#pragma unroll
                for (int j = 0; j < 4; j++) cc[nt][j] *= scale;
                cm0 = fmaxf(cm0, fmaxf(cc[nt][0], cc[nt][1]));
                cm1 = fmaxf(cm1, fmaxf(cc[nt][2], cc[nt][3]));
            }
            cm0 = fmaxf(cm0, __shfl_xor_sync(0xffffffffu, cm0, 1));
            cm0 = fmaxf(cm0, __shfl_xor_sync(0xffffffffu, cm0, 2));
            cm1 = fmaxf(cm1, __shfl_xor_sync(0xffffffffu, cm1, 1));
            cm1 = fmaxf(cm1, __shfl_xor_sync(0xffffffffu, cm1, 2));
            float M0 = fmaxf(m0, cm0), M1 = fmaxf(m1, cm1);
            float p0 = 0.f, p1 = 0.f;
#pragma unroll
            for (int nt = 0; nt < 8; nt++) {
                p0 += __expf(cc[nt][0] - M0) + __expf(cc[nt][1] - M0);
                p1 += __expf(cc[nt][2] - M1) + __expf(cc[nt][3] - M1);
            }
            p0 += __shfl_xor_sync(0xffffffffu, p0, 1);
            p0 += __shfl_xor_sync(0xffffffffu, p0, 2);
            p1 += __shfl_xor_sync(0xffffffffu, p1, 1);
            p1 += __shfl_xor_sync(0xffffffffu, p1, 2);
            l0 = l0 * __expf(m0 - M0) + p0;  m0 = M0;
            l1 = l1 * __expf(m1 - M1) + p1;  m1 = M1;
        }
        if (qc == 0) {
            Mv[t0 + qr]     = m0;  Lv[t0 + qr]     = 1.f / l0;
            Mv[t0 + qr + 8] = m1;  Lv[t0 + qr + 8] = 1.f / l1;
        }
    }
    __syncthreads();

    // ---------------- Pass 2: output ----------------
    __half* Pwh = Pshi + wid * (16 * 24);
    __half* Pwl = Pslo + wid * (16 * 24);
    const uint32_t PwhA = smem_u32(Pwh);
    const uint32_t PwlA = smem_u32(Pwl);
    for (int sb = wid; sb < nb; sb += 8) {
        const int s0 = sb * 16;
        unsigned vh[2][4], vl[2][4];
#pragma unroll
        for (int ks = 0; ks < 2; ks++) {
            uint32_t rv = VhiA + (((uint32_t)s0 + ro) * 40 + ks*16 + co) * 2;
            ldsm4(vh[ks], rv);
            ldsm4(vl[ks], rv + KVoff);
        }
        float o[4][4];
#pragma unroll
        for (int ni = 0; ni < 4; ni++)
#pragma unroll
            for (int j = 0; j < 4; j++) o[ni][j] = 0.f;

        for (int t0 = 0; t0 < T; t0 += 16) {
            float e[2][4];
#pragma unroll
            for (int nt = 0; nt < 2; nt++)
#pragma unroll
                for (int j = 0; j < 4; j++) e[nt][j] = 0.f;
#pragma unroll
            for (int ks = 0; ks < 2; ks++) {
                uint32_t rk = KhiA + (((uint32_t)t0 + ro) * 40 + ks*16 + co) * 2;
                unsigned kh4[4], kl4[4];
                ldsm4(kh4, rk);
                ldsm4(kl4, rk + KVoff);
                mma_f16(e[0], vh[ks], kh4[0], kh4[2]);
                mma_f16(e[0], vh[ks], kl4[0], kl4[2]);
                mma_f16(e[0], vl[ks], kh4[0], kh4[2]);
                mma_f16(e[1], vh[ks], kh4[1], kh4[3]);
                mma_f16(e[1], vh[ks], kl4[1], kl4[3]);
                mma_f16(e[1], vl[ks], kh4[1], kh4[3]);
            }
            __syncwarp();
#pragma unroll
            for (int nt = 0; nt < 2; nt++) {
                int tc = t0 + nt * 8 + 2 * qc;
                float mva = Mv[tc],   lva = Lv[tc];
                float mvb = Mv[tc+1], lvb = Lv[tc+1];
                float e0 = __expf(e[nt][0] * scale - mva) * lva;
                float e1 = __expf(e[nt][1] * scale - mvb) * lvb;
                float e2 = __expf(e[nt][2] * scale - mva) * lva;
                float e3 = __expf(e[nt][3] * scale - mvb) * lvb;
                __half h0, h1, h2, h3, g0, g1, g2, g3;
                split_h(e0, h0, g0); split_h(e1, h1, g1);
                split_h(e2, h2, g2); split_h(e3, h3, g3);
                *(unsigned*)(Pwh + qr*24     + nt*8 + 2*qc) = pack2(h0, h1);
                *(unsigned*)(Pwh + (qr+8)*24 + nt*8 + 2*qc) = pack2(h2, h3);
                *(unsigned*)(Pwl + qr*24     + nt*8 + 2*qc) = pack2(g0, g1);
                *(unsigned*)(Pwl + (qr+8)*24 + nt*8 + 2*qc) = pack2(g2, g3);
            }
            __syncwarp();
            unsigned ph[4], pl[4];
            ldsm4(ph, PwhA + (ro*24 + co) * 2);
            ldsm4(pl, PwlA + (ro*24 + co) * 2);
#pragma unroll
            for (int p2 = 0; p2 < 2; p2++) {
                uint32_t rq = QhiA + ((p2*16 + ro) * (uint32_t)QS + (uint32_t)t0 + co) * 2;
                unsigned q4[4], q4l[4];
                ldsm4(q4,  rq);
                ldsm4(q4l, rq + Qoff);
                mma_f16(o[2*p2],   ph, q4[0], q4[2]);
                mma_f16(o[2*p2],   ph, q4l[0], q4l[2]);
                mma_f16(o[2*p2],   pl, q4[0], q4[2]);
                mma_f16(o[2*p2+1], ph, q4[1], q4[3]);
                mma_f16(o[2*p2+1], ph, q4l[1], q4l[3]);
                mma_f16(o[2*p2+1], pl, q4[1], q4[3]);
            }
        }
#pragma unroll
        for (int ni = 0; ni < 4; ni++) {
            int icol = ni * 8 + 2 * qc;
            int srow = s0 + qr;
            size_t base = off + (size_t)icol * T + srow;
            if (addend != nullptr) {
                Ob[base]         = o[ni][0] + addend[base];
                Ob[base + T]     = o[ni][1] + addend[base + T];
                Ob[base + 8]     = o[ni][2] + addend[base + 8];
                Ob[base + T + 8] = o[ni][3] + addend[base + T + 8];
            } else {
                Ob[base]         = o[ni][0];
                Ob[base + T]     = o[ni][1];
                Ob[base + 8]     = o[ni][2];
                Ob[base + T + 8] = o[ni][3];
            }
        }
    }
}

// ---------------------------------------------------------------------------
// LayerNorm: one warp per 512-wide row; emits split fp16 directly.
// ---------------------------------------------------------------------------
__global__ __launch_bounds__(256) void ln_kernel(
    const float* __restrict__ X, const float* __restrict__ gw,
    const float* __restrict__ gb, __half* __restrict__ Yh, __half* __restrict__ Yl)
{
    const int row  = blockIdx.x * 8 + (threadIdx.x >> 5);
    const int lane = threadIdx.x & 31;
    const float4* xr = (const float4*)(X + (size_t)row * D_);
    float4 v[4];
    float s = 0.f, ss = 0.f;
#pragma unroll
    for (int w = 0; w < 4; w++) {
        v[w] = xr[w*32 + lane];
        s  += v[w].x + v[w].y + v[w].z + v[w].w;
        ss += v[w].x*v[w].x + v[w].y*v[w].y + v[w].z*v[w].z + v[w].w*v[w].w;
    }
#pragma unroll
    for (int o = 16; o > 0; o >>= 1) {
        s  += __shfl_xor_sync(0xffffffffu, s, o);
        ss += __shfl_xor_sync(0xffffffffu, ss, o);
    }
    const float mean = s * (1.f/512.f);
    const float var  = ss * (1.f/512.f) - mean*mean;
    const float r = rsqrtf(var + 1e-5f);
    const float4* gr = (const float4*)gw;
    const float4* br = (const float4*)gb;
#pragma unroll
    for (int w = 0; w < 4; w++) {
        float4 gv = gr[w*32 + lane];
        float4 bv = br[w*32 + lane];
        float o0 = (v[w].x - mean) * r * gv.x + bv.x;
        float o1 = (v[w].y - mean) * r * gv.y + bv.y;
        float o2 = (v[w].z - mean) * r * gv.z + bv.z;
        float o3 = (v[w].w - mean) * r * gv.w + bv.w;
        __half h0,h1,h2,h3,l0,l1,l2,l3;
        split_h(o0,h0,l0); split_h(o1,h1,l1); split_h(o2,h2,l2); split_h(o3,h3,l3);
        size_t idx = (size_t)row * D_ + (w*32 + lane) * 4;
        *(uint2*)(Yh + idx) = make_uint2(pack2(h0,h1), pack2(h2,h3));
        *(uint2*)(Yl + idx) = make_uint2(pack2(l0,l1), pack2(l2,l3));
    }
}

// ---------------------------------------------------------------------------
// Combine: out = t1*sig(ld) + t2*(1-sig(ld)), ld = (t1-t2)@fw^T (bias cancels)
// ---------------------------------------------------------------------------
__global__ __launch_bounds__(256) void fuse2_kernel(
    const float4* __restrict__ t1, const float4* __restrict__ t2,
    const float4* __restrict__ ld, float4* __restrict__ out)
{
    int i = blockIdx.x * 256 + threadIdx.x;
    float4 x1 = t1[i], x2 = t2[i], d = ld[i];
    float a0 = 1.f / (1.f + __expf(-d.x));
    float a1 = 1.f / (1.f + __expf(-d.y));
    float a2 = 1.f / (1.f + __expf(-d.z));
    float a3 = 1.f / (1.f + __expf(-d.w));
    float4 o;
    o.x = x1.x * a0 + x2.x * (1.f - a0);
    o.y = x1.y * a1 + x2.y * (1.f - a1);
    o.z = x1.z * a2 + x2.z * (1.f - a2);
    o.w = x1.w * a3 + x2.w * (1.f - a3);
    out[i] = o;
}

// ---------------------------------------------------------------------------
extern "C" void kernel_launch(void* const* d_in, const int* in_sizes, int n_in,
                              void* d_out, int out_size)
{
    (void)in_sizes; (void)n_in; (void)out_size;
    const float* x    = (const float*)d_in[0];
    const float* qw   = (const float*)d_in[1];
    const float* qb   = (const float*)d_in[2];
    const float* kw   = (const float*)d_in[3];
    const float* kb   = (const float*)d_in[4];
    const float* vw   = (const float*)d_in[5];
    const float* vb   = (const float*)d_in[6];
    const float* temp = (const float*)d_in[7];
    const float* lng  = (const float*)d_in[8];
    const float* lnb  = (const float*)d_in[9];
    const float* fw   = (const float*)d_in[10];
    (void)d_in[11];   // fusion bias cancels in the softmax difference
    float* out = (float*)d_out;

    float *xr, *t1, *t2, *a1;
    __half *qh,*ql,*kh2,*kl2,*vh2,*vl2, *q2h,*q2l,*k2h,*k2l,*v2h,*v2l;
    __half *xh, *xl, *lnh, *lnl, *dh, *dl, *wh, *wl;
    cudaGetSymbolAddress((void**)&xr, g_xr);
    cudaGetSymbolAddress((void**)&t1, g_t1);
    cudaGetSymbolAddress((void**)&t2, g_t2);
    cudaGetSymbolAddress((void**)&a1, g_a1);
    cudaGetSymbolAddress((void**)&qh, g_qh);   cudaGetSymbolAddress((void**)&ql, g_ql);
    cudaGetSymbolAddress((void**)&kh2, g_kh);  cudaGetSymbolAddress((void**)&kl2, g_kl);
    cudaGetSymbolAddress((void**)&vh2, g_vh);  cudaGetSymbolAddress((void**)&vl2, g_vl);
    cudaGetSymbolAddress((void**)&q2h, g_q2h); cudaGetSymbolAddress((void**)&q2l, g_q2l);
    cudaGetSymbolAddress((void**)&k2h, g_k2h); cudaGetSymbolAddress((void**)&k2l, g_k2l);
    cudaGetSymbolAddress((void**)&v2h, g_v2h); cudaGetSymbolAddress((void**)&v2l, g_v2l);
    cudaGetSymbolAddress((void**)&xh, g_xh);   cudaGetSymbolAddress((void**)&xl, g_xl);
    cudaGetSymbolAddress((void**)&lnh, g_lnh); cudaGetSymbolAddress((void**)&lnl, g_lnl);
    cudaGetSymbolAddress((void**)&dh, g_dh);   cudaGetSymbolAddress((void**)&dl, g_dl);
    cudaGetSymbolAddress((void**)&wh, g_wh);   cudaGetSymbolAddress((void**)&wl, g_wl);

    const int gemmSmem = 16 * ABYTES;                                   // 163840
    // attn smem: K/V 4*[T][40] halves + Q 2*[32][T+8] + stats + P scratch
    const int smem384 = (4*384*40 + 2*32*392) * 2 + 2*384*4 + (2*8*16*24) * 2;  // 188416
    const int smem128 = (4*128*40 + 2*32*136) * 2 + 2*128*4 + (2*8*16*24) * 2;  // 71680
    cudaFuncSetAttribute(gemm_tc, cudaFuncAttributeMaxDynamicSharedMemorySize, gemmSmem);
    cudaFuncSetAttribute(attn_tc, cudaFuncAttributeMaxDynamicSharedMemorySize, smem384);

    // 1) pre-split x and all weight matrices
    SpArgs sp1;
    sp1.e[0] = { x,  xh,          xl,          BTD    };
    sp1.e[1] = { qw, wh + 0,      wl + 0,      5*WKN  };
    sp1.e[2] = { kw, wh + (size_t)5*WKN,  wl + (size_t)5*WKN,  5*WKN  };
    sp1.e[3] = { vw, wh + (size_t)10*WKN, wl + (size_t)10*WKN, 5*WKN  };
    sp1.e[4] = { fw, wh + (size_t)15*WKN, wl + (size_t)15*WKN, WKN    };
    split_kernel<<<dim3(512, 1, 5), 256>>>(sp1);

    // 2) QKV GEMMs (block0 full-T + blocks1-3 chunked), split epilogue
    G5Args ga1;
    ga1.s[0] = { xh, xl, 0,  0, qb, nullptr, qh,  ql,  0, 1 };
    ga1.s[1] = { xh, xl, 5,  0, kb, nullptr, kh2, kl2, 0, 1 };
    ga1.s[2] = { xh, xl, 10, 0, vb, nullptr, vh2, vl2, 0, 1 };
    ga1.s[3] = { xh, xl, 0,  0, qb, nullptr, q2h, q2l, 1, 1 };
    ga1.s[4] = { xh, xl, 5,  0, kb, nullptr, k2h, k2l, 1, 1 };
    ga1.s[5] = { xh, xl, 10, 0, vb, nullptr, v2h, v2l, 1, 1 };
    gemm_tc<<<dim3(4, 96, 6), 256, gemmSmem>>>(ga1);

    attn_tc<<<dim3(H_, 1, B_), 256, smem384>>>(qh, ql, kh2, kl2, vh2, vl2, temp, nullptr, xr, 384, 0);
    attn_tc<<<dim3(H_, 3, B_), 256, smem128>>>(q2h, q2l, k2h, k2l, v2h, v2l, temp, xr, t1, 128, 1);

    // 3) LayerNorm(t1) -> split fp16
    ln_kernel<<<M_/8, 256>>>(t1, lng, lnb, lnh, lnl);

    // 4) block4 QKV on LN output (reuse half buffers)
    G5Args ga2;
    ga2.s[0] = { lnh, lnl, 0,  4, qb, nullptr, qh,  ql,  0, 1 };
    ga2.s[1] = { lnh, lnl, 5,  4, kb, nullptr, kh2, kl2, 0, 1 };
    ga2.s[2] = { lnh, lnl, 10, 4, vb, nullptr, vh2, vl2, 0, 1 };
    ga2.s[3] = ga2.s[0]; ga2.s[4] = ga2.s[0]; ga2.s[5] = ga2.s[0];
    gemm_tc<<<dim3(4, 96, 3), 256, gemmSmem>>>(ga2);

    attn_tc<<<dim3(H_, 1, B_), 256, smem384>>>(qh, ql, kh2, kl2, vh2, vl2, temp, xr, t2, 384, 4);

    // 5) fusion: single GEMM on the difference (bias cancels in softmax)
    diff_split_kernel<<<BTD/4/256, 256>>>((const float4*)t1, (const float4*)t2, dh, dl);
    G5Args ga3;
    ga3.s[0] = { dh, dl, 15, 0, nullptr, a1, nullptr, nullptr, 0, 0 };
    ga3.s[1] = ga3.s[0]; ga3.s[2] = ga3.s[0]; ga3.s[3] = ga3.s[0];
    ga3.s[4] = ga3.s[0]; ga3.s[5] = ga3.s[0];
    gemm_tc<<<dim3(4, 96, 1), 256, gemmSmem>>>(ga3);

    fuse2_kernel<<<BTD/4/256, 256>>>((const float4*)t1, (const float4*)t2,
                                     (const float4*)a1, (float4*)out);
}

// round 8
// speedup vs baseline: 2.6458x; 1.0028x over previous
#include <cuda_runtime.h>
#include <cuda_fp16.h>
#include <math.h>
#include <stdint.h>

#define B_  32
#define T_  384
#define D_  512
#define H_  16
#define BTD (B_*T_*D_)     // 6291456
#define M_  (B_*T_)        // 12288
#define WKN (512*512)

// ---------------- scratch (static device globals; no cudaMalloc) ----------
__device__ float g_xr[BTD], g_t1[BTD], g_t2[BTD], g_a1[BTD];
__device__ __half g_qh[BTD], g_ql[BTD], g_kh[BTD], g_kl[BTD], g_vh[BTD], g_vl[BTD];
__device__ __half g_q2h[BTD], g_q2l[BTD], g_k2h[BTD], g_k2l[BTD], g_v2h[BTD], g_v2l[BTD];
__device__ __half g_xh[BTD],  g_xl[BTD];
__device__ __half g_lnh[BTD], g_lnl[BTD];
__device__ __half g_dh[BTD],  g_dl[BTD];
__device__ __half g_wh[16*WKN], g_wl[16*WKN];   // [qw0-4 | kw0-4 | vw0-4 | fw]

// ---------------- helpers --------------------------------------------------
__device__ __forceinline__ void split_h(float x, __half& hi, __half& lo) {
    hi = __float2half_rn(x);
    lo = __float2half_rn(x - __half2float(hi));
}
__device__ __forceinline__ unsigned pack2(__half a, __half b) {
    __half2 h = __halves2half2(a, b);
    return *reinterpret_cast<unsigned*>(&h);
}
__device__ __forceinline__ void mma_f16(float* c, const unsigned* a, unsigned b0, unsigned b1) {
    asm volatile("mma.sync.aligned.m16n8k16.row.col.f32.f16.f16.f32 "
        "{%0,%1,%2,%3}, {%4,%5,%6,%7}, {%8,%9}, {%0,%1,%2,%3};"
        : "+f"(c[0]), "+f"(c[1]), "+f"(c[2]), "+f"(c[3])
        : "r"(a[0]), "r"(a[1]), "r"(a[2]), "r"(a[3]), "r"(b0), "r"(b1));
}
__device__ __forceinline__ void ldsm4(unsigned* r, uint32_t addr) {
    asm volatile("ldmatrix.sync.aligned.m8n8.x4.shared.b16 {%0,%1,%2,%3}, [%4];"
        : "=r"(r[0]), "=r"(r[1]), "=r"(r[2]), "=r"(r[3]) : "r"(addr));
}
__device__ __forceinline__ uint32_t smem_u32(const void* p) {
    uint32_t a;
    asm("{ .reg .u64 t; cvta.to.shared.u64 t, %1; cvt.u32.u64 %0, t; }" : "=r"(a) : "l"(p));
    return a;
}
__device__ __forceinline__ void cpa16(uint32_t dst, const void* src) {
    asm volatile("cp.async.cg.shared.global [%0], [%1], 16;" :: "r"(dst), "l"(src) : "memory");
}

// ---------------------------------------------------------------------------
// fp16-split GEMM: CTA tile 128x256, 8 warps at 64x64 each, k-chunk 32,
// 3-stage cp.async pipeline, ldmatrix operand loads. High arithmetic
// intensity per smem byte (0.042 B/MAC reads) to escape the 128 B/cyc/SM
// crossbar bound. split=1: 3-mma hi/lo; split=0: single fp16.
// ---------------------------------------------------------------------------
#define STAGE_B 61440u    // Ahi 10240 | Alo 10240 | Whi 20480 | Wlo 20480
struct G5 { const __half* Ah; const __half* Al; int wbase; int wadd;
            const float* bias; float* C; __half* Chi; __half* Clo;
            int chunk; int split; };
struct G5Args { G5 s[6]; };

__global__ __launch_bounds__(256) void gemm_tc(G5Args ga)
{
    extern __shared__ __half smh[];
    const uint32_t sm32 = smem_u32(smh);
    const int tid = threadIdx.x, lane = tid & 31, wid = tid >> 5;
    const int wm = wid & 1, wn = wid >> 1;            // 2 x 4 warps
    const int qr = lane >> 2, qc = lane & 3;
    const uint32_t ro = (lane & 7) + ((lane >> 3) & 1) * 8;
    const uint32_t co = (lane >> 4) * 8;

    const G5 sl = ga.s[blockIdx.z];
    const int m0 = blockIdx.y * 128, n0 = blockIdx.x * 256;
    const int widx = sl.chunk ? (1 + (m0 % 384) / 128) : sl.wadd;
    const __half* Wh = g_wh + (size_t)(sl.wbase + widx) * WKN;
    const __half* Wl = g_wl + (size_t)(sl.wbase + widx) * WKN;
    const float*  bp = sl.bias ? sl.bias + widx * 512 : nullptr;
    const int split = sl.split;

    auto issue = [&](int c) {
        const uint32_t base = sm32 + (uint32_t)(c % 3) * STAGE_B;
        const int kb = c * 32;
#pragma unroll
        for (int r = 0; r < 2; r++) {                 // A: 128 rows
            int e = tid + r * 256;
            int row = e >> 2, seg = e & 3;
            uint32_t d = base + row * 80 + seg * 16;
            size_t gA = (size_t)(m0 + row) * 512 + kb + seg * 8;
            cpa16(d, sl.Ah + gA);
            if (split) cpa16(d + 10240, sl.Al + gA);
        }
#pragma unroll
        for (int r = 0; r < 4; r++) {                 // W: 256 rows
            int e = tid + r * 256;
            int row = e >> 2, seg = e & 3;
            uint32_t d = base + 20480 + row * 80 + seg * 16;
            size_t gW = (size_t)(n0 + row) * 512 + kb + seg * 8;
            cpa16(d, Wh + gW);
            if (split) cpa16(d + 20480, Wl + gW);
        }
    };

    float acc[4][8][4];
#pragma unroll
    for (int mi = 0; mi < 4; mi++)
#pragma unroll
        for (int ni = 0; ni < 8; ni++)
#pragma unroll
            for (int j = 0; j < 4; j++) acc[mi][ni][j] = 0.f;

    issue(0);
    asm volatile("cp.async.commit_group;" ::: "memory");
    issue(1);
    asm volatile("cp.async.commit_group;" ::: "memory");

    for (int c = 0; c < 16; c++) {
        asm volatile("cp.async.wait_group 1;" ::: "memory");
        __syncthreads();
        const uint32_t sA = sm32 + (uint32_t)(c % 3) * STAGE_B;
        const uint32_t sW = sA + 20480;
#pragma unroll
        for (int ks = 0; ks < 2; ks++) {
            unsigned ah[4][4], al[4][4];
#pragma unroll
            for (int mi = 0; mi < 4; mi++) {
                uint32_t ra = sA + ((wm*64 + mi*16 + ro) * 40 + ks*16 + co) * 2;
                ldsm4(ah[mi], ra);
                if (split) ldsm4(al[mi], ra + 10240);
            }
#pragma unroll
            for (int p = 0; p < 4; p++) {
                uint32_t rw = sW + ((wn*64 + p*16 + ro) * 40 + ks*16 + co) * 2;
                unsigned wh4[4], wl4[4];
                ldsm4(wh4, rw);
                if (split) ldsm4(wl4, rw + 20480);
#pragma unroll
                for (int mi = 0; mi < 4; mi++) {
                    mma_f16(acc[mi][2*p],   ah[mi], wh4[0], wh4[2]);
                    mma_f16(acc[mi][2*p+1], ah[mi], wh4[1], wh4[3]);
                    if (split) {
                        mma_f16(acc[mi][2*p],   ah[mi], wl4[0], wl4[2]);
                        mma_f16(acc[mi][2*p],   al[mi], wh4[0], wh4[2]);
                        mma_f16(acc[mi][2*p+1], ah[mi], wl4[1], wl4[3]);
                        mma_f16(acc[mi][2*p+1], al[mi], wh4[1], wh4[3]);
                    }
                }
            }
        }
        if (c + 2 < 16) issue(c + 2);
        asm volatile("cp.async.commit_group;" ::: "memory");
    }

    // epilogue
#pragma unroll
    for (int mi = 0; mi < 4; mi++) {
#pragma unroll
        for (int ni = 0; ni < 8; ni++) {
            int row = m0 + wm * 64 + mi * 16 + qr;
            int col = n0 + wn * 64 + ni * 8 + 2 * qc;
            float bx = 0.f, by = 0.f;
            if (bp) { float2 bb = *(const float2*)(bp + col); bx = bb.x; by = bb.y; }
            float v00 = acc[mi][ni][0] + bx, v01 = acc[mi][ni][1] + by;
            float v10 = acc[mi][ni][2] + bx, v11 = acc[mi][ni][3] + by;
            if (sl.Chi) {
                __half h0,h1,l0,l1;
                split_h(v00,h0,l0); split_h(v01,h1,l1);
                *(unsigned*)(sl.Chi + (size_t)row*512 + col) = pack2(h0,h1);
                *(unsigned*)(sl.Clo + (size_t)row*512 + col) = pack2(l0,l1);
                split_h(v10,h0,l0); split_h(v11,h1,l1);
                *(unsigned*)(sl.Chi + (size_t)(row+8)*512 + col) = pack2(h0,h1);
                *(unsigned*)(sl.Clo + (size_t)(row+8)*512 + col) = pack2(l0,l1);
            } else {
                float2 o0 = { v00, v01 }, o1 = { v10, v11 };
                *(float2*)(sl.C + (size_t)row * 512 + col)       = o0;
                *(float2*)(sl.C + (size_t)(row + 8) * 512 + col) = o1;
            }
        }
    }
}

// ---------------------------------------------------------------------------
// split kernels: f32 -> (hi, lo) fp16 pairs
// ---------------------------------------------------------------------------
struct SpEnt { const float* src; __half* hi; __half* lo; int n; };
struct SpArgs { SpEnt e[5]; };

__global__ __launch_bounds__(256) void split_kernel(SpArgs sa)
{
    SpEnt E = sa.e[blockIdx.z];
    int stride = gridDim.x * 256;
    for (int i = blockIdx.x * 256 + threadIdx.x; i * 4 < E.n; i += stride) {
        float4 v = ((const float4*)E.src)[i];
        __half h0,h1,h2,h3,l0,l1,l2,l3;
        split_h(v.x,h0,l0); split_h(v.y,h1,l1); split_h(v.z,h2,l2); split_h(v.w,h3,l3);
        *(uint2*)(E.hi + 4*i) = make_uint2(pack2(h0,h1), pack2(h2,h3));
        *(uint2*)(E.lo + 4*i) = make_uint2(pack2(l0,l1), pack2(l2,l3));
    }
}

// diff+split: d = t1 - t2 -> (hi, lo)
__global__ __launch_bounds__(256) void diff_split_kernel(
    const float4* __restrict__ t1, const float4* __restrict__ t2,
    __half* __restrict__ hi, __half* __restrict__ lo)
{
    int i = blockIdx.x * 256 + threadIdx.x;
    float4 a = t1[i], b = t2[i];
    __half h0,h1,h2,h3,l0,l1,l2,l3;
    split_h(a.x-b.x,h0,l0); split_h(a.y-b.y,h1,l1);
    split_h(a.z-b.z,h2,l2); split_h(a.w-b.w,h3,l3);
    *(uint2*)(hi + 4*i) = make_uint2(pack2(h0,h1), pack2(h2,h3));
    *(uint2*)(lo + 4*i) = make_uint2(pack2(l0,l1), pack2(l2,l3));
}

// ---------------------------------------------------------------------------
// fp16-split attention with ldmatrix operand loads (unchanged from R7).
// ---------------------------------------------------------------------------
__global__ __launch_bounds__(256) void attn_tc(
    const __half* __restrict__ Qbh, const __half* __restrict__ Qbl,
    const __half* __restrict__ Kbh, const __half* __restrict__ Kbl,
    const __half* __restrict__ Vbh, const __half* __restrict__ Vbl,
    const float* __restrict__ temp,
    const float* __restrict__ addend, float* __restrict__ Ob,
    int T, int tempBase)
{
    extern __shared__ __half smh[];
    const int QS = T + 8;
    __half* Khi = smh;                       // [T][40]
    __half* Klo = Khi + T * 40;
    __half* Vhi = Klo + T * 40;
    __half* Vlo = Vhi + T * 40;
    __half* Qhi = Vlo + T * 40;              // [32][QS]
    __half* Qlo = Qhi + 32 * QS;
    float*  Mv  = (float*)(Qlo + 32 * QS);
    float*  Lv  = Mv + T;
    __half* Pshi = (__half*)(Lv + T);        // 8 warps * [16][24]
    __half* Pslo = Pshi + 8 * 16 * 24;

    const uint32_t smA   = smem_u32(smh);
    const uint32_t KVoff = (uint32_t)T * 80;
    const uint32_t Qoff  = (uint32_t)32 * QS * 2;

    const int h = blockIdx.x, c = blockIdx.y, b = blockIdx.z;
    const int tid = threadIdx.x, lane = tid & 31, wid = tid >> 5;
    const int qr = lane >> 2, qc = lane & 3;
    const uint32_t ro = (lane & 7) + ((lane >> 3) & 1) * 8;
    const uint32_t co = (lane >> 4) * 8;
    const size_t off = (size_t)b * (T_*D_) + (size_t)c * (128*D_) + (size_t)h * 32 * T;
    const float scale = temp[(tempBase + c) * H_ + h];

    for (int idx = tid; idx < 32 * T; idx += 256) {
        int i = idx / T, t = idx - i * T;
        Khi[t*40 + i] = Kbh[off + idx];
        Klo[t*40 + i] = Kbl[off + idx];
        Vhi[t*40 + i] = Vbh[off + idx];
        Vlo[t*40 + i] = Vbl[off + idx];
        Qhi[i*QS + t] = Qbh[off + idx];
        Qlo[i*QS + t] = Qbl[off + idx];
    }
    __syncthreads();

    const int nb = T >> 4;
    const uint32_t KhiA = smA;
    const uint32_t VhiA = smA + 2 * KVoff;
    const uint32_t QhiA = smA + 4 * KVoff;

    // ---------------- Pass 1: row stats ----------------
    for (int tb = wid; tb < nb; tb += 8) {
        const int t0 = tb * 16;
        unsigned ah[2][4], al[2][4];
#pragma unroll
        for (int ks = 0; ks < 2; ks++) {
            uint32_t ra = KhiA + (((uint32_t)t0 + ro) * 40 + ks*16 + co) * 2;
            ldsm4(ah[ks], ra);
            ldsm4(al[ks], ra + KVoff);
        }
        float m0 = -3.0e38f, m1 = -3.0e38f, l0 = 0.f, l1 = 0.f;
        for (int s0 = 0; s0 < T; s0 += 64) {
            float cc[8][4];
#pragma unroll
            for (int nt = 0; nt < 8; nt++)
#pragma unroll
                for (int j = 0; j < 4; j++) cc[nt][j] = 0.f;
#pragma unroll
            for (int ks = 0; ks < 2; ks++) {
#pragma unroll
                for (int p = 0; p < 4; p++) {
                    uint32_t rv = VhiA + (((uint32_t)(s0 + p*16) + ro) * 40 + ks*16 + co) * 2;
                    unsigned vh4[4], vl4[4];
                    ldsm4(vh4, rv);
                    ldsm4(vl4, rv + KVoff);
                    mma_f16(cc[2*p],   ah[ks], vh4[0], vh4[2]);
                    mma_f16(cc[2*p],   ah[ks], vl4[0], vl4[2]);
                    mma_f16(cc[2*p],   al[ks], vh4[0], vh4[2]);
                    mma_f16(cc[2*p+1], ah[ks], vh4[1], vh4[3]);
                    mma_f16(cc[2*p+1], ah[ks], vl4[1], vl4[3]);
                    mma_f16(cc[2*p+1], al[ks], vh4[1], vh4[3]);
                }
            }
            float cm0 = -3.0e38f, cm1 = -3.0e38f;
#pragma unroll
            for (int nt = 0; nt < 8; nt++) {
#pragma unroll
                for (int j = 0; j < 4; j++) cc[nt][j] *= scale;
                cm0 = fmaxf(cm0, fmaxf(cc[nt][0], cc[nt][1]));
                cm1 = fmaxf(cm1, fmaxf(cc[nt][2], cc[nt][3]));
            }
            cm0 = fmaxf(cm0, __shfl_xor_sync(0xffffffffu, cm0, 1));
            cm0 = fmaxf(cm0, __shfl_xor_sync(0xffffffffu, cm0, 2));
            cm1 = fmaxf(cm1, __shfl_xor_sync(0xffffffffu, cm1, 1));
            cm1 = fmaxf(cm1, __shfl_xor_sync(0xffffffffu, cm1, 2));
            float M0 = fmaxf(m0, cm0), M1 = fmaxf(m1, cm1);
            float p0 = 0.f, p1 = 0.f;
#pragma unroll
            for (int nt = 0; nt < 8; nt++) {
                p0 += __expf(cc[nt][0] - M0) + __expf(cc[nt][1] - M0);
                p1 += __expf(cc[nt][2] - M1) + __expf(cc[nt][3] - M1);
            }
            p0 += __shfl_xor_sync(0xffffffffu, p0, 1);
            p0 += __shfl_xor_sync(0xffffffffu, p0, 2);
            p1 += __shfl_xor_sync(0xffffffffu, p1, 1);
            p1 += __shfl_xor_sync(0xffffffffu, p1, 2);
            l0 = l0 * __expf(m0 - M0) + p0;  m0 = M0;
            l1 = l1 * __expf(m1 - M1) + p1;  m1 = M1;
        }
        if (qc == 0) {
            Mv[t0 + qr]     = m0;  Lv[t0 + qr]     = 1.f / l0;
            Mv[t0 + qr + 8] = m1;  Lv[t0 + qr + 8] = 1.f / l1;
        }
    }
    __syncthreads();

    // ---------------- Pass 2: output ----------------
    __half* Pwh = Pshi + wid * (16 * 24);
    __half* Pwl = Pslo + wid * (16 * 24);
    const uint32_t PwhA = smem_u32(Pwh);
    const uint32_t PwlA = smem_u32(Pwl);
    for (int sb = wid; sb < nb; sb += 8) {
        const int s0 = sb * 16;
        unsigned vh[2][4], vl[2][4];
#pragma unroll
        for (int ks = 0; ks < 2; ks++) {
            uint32_t rv = VhiA + (((uint32_t)s0 + ro) * 40 + ks*16 + co) * 2;
            ldsm4(vh[ks], rv);
            ldsm4(vl[ks], rv + KVoff);
        }
        float o[4][4];
#pragma unroll
        for (int ni = 0; ni < 4; ni++)
#pragma unroll
            for (int j = 0; j < 4; j++) o[ni][j] = 0.f;

        for (int t0 = 0; t0 < T; t0 += 16) {
            float e[2][4];
#pragma unroll
            for (int nt = 0; nt < 2; nt++)
#pragma unroll
                for (int j = 0; j < 4; j++) e[nt][j] = 0.f;
#pragma unroll
            for (int ks = 0; ks < 2; ks++) {
                uint32_t rk = KhiA + (((uint32_t)t0 + ro) * 40 + ks*16 + co) * 2;
                unsigned kh4[4], kl4[4];
                ldsm4(kh4, rk);
                ldsm4(kl4, rk + KVoff);
                mma_f16(e[0], vh[ks], kh4[0], kh4[2]);
                mma_f16(e[0], vh[ks], kl4[0], kl4[2]);
                mma_f16(e[0], vl[ks], kh4[0], kh4[2]);
                mma_f16(e[1], vh[ks], kh4[1], kh4[3]);
                mma_f16(e[1], vh[ks], kl4[1], kl4[3]);
                mma_f16(e[1], vl[ks], kh4[1], kh4[3]);
            }
            __syncwarp();
#pragma unroll
            for (int nt = 0; nt < 2; nt++) {
                int tc = t0 + nt * 8 + 2 * qc;
                float mva = Mv[tc],   lva = Lv[tc];
                float mvb = Mv[tc+1], lvb = Lv[tc+1];
                float e0 = __expf(e[nt][0] * scale - mva) * lva;
                float e1 = __expf(e[nt][1] * scale - mvb) * lvb;
                float e2 = __expf(e[nt][2] * scale - mva) * lva;
                float e3 = __expf(e[nt][3] * scale - mvb) * lvb;
                __half h0, h1, h2, h3, g0, g1, g2, g3;
                split_h(e0, h0, g0); split_h(e1, h1, g1);
                split_h(e2, h2, g2); split_h(e3, h3, g3);
                *(unsigned*)(Pwh + qr*24     + nt*8 + 2*qc) = pack2(h0, h1);
                *(unsigned*)(Pwh + (qr+8)*24 + nt*8 + 2*qc) = pack2(h2, h3);
                *(unsigned*)(Pwl + qr*24     + nt*8 + 2*qc) = pack2(g0, g1);
                *(unsigned*)(Pwl + (qr+8)*24 + nt*8 + 2*qc) = pack2(g2, g3);
            }
            __syncwarp();
            unsigned ph[4], pl[4];
            ldsm4(ph, PwhA + (ro*24 + co) * 2);
            ldsm4(pl, PwlA + (ro*24 + co) * 2);
#pragma unroll
            for (int p2 = 0; p2 < 2; p2++) {
                uint32_t rq = QhiA + ((p2*16 + ro) * (uint32_t)QS + (uint32_t)t0 + co) * 2;
                unsigned q4[4], q4l[4];
                ldsm4(q4,  rq);
                ldsm4(q4l, rq + Qoff);
                mma_f16(o[2*p2],   ph, q4[0], q4[2]);
                mma_f16(o[2*p2],   ph, q4l[0], q4l[2]);
                mma_f16(o[2*p2],   pl, q4[0], q4[2]);
                mma_f16(o[2*p2+1], ph, q4[1], q4[3]);
                mma_f16(o[2*p2+1], ph, q4l[1], q4l[3]);
                mma_f16(o[2*p2+1], pl, q4[1], q4[3]);
            }
        }
#pragma unroll
        for (int ni = 0; ni < 4; ni++) {
            int icol = ni * 8 + 2 * qc;
            int srow = s0 + qr;
            size_t base = off + (size_t)icol * T + srow;
            if (addend != nullptr) {
                Ob[base]         = o[ni][0] + addend[base];
                Ob[base + T]     = o[ni][1] + addend[base + T];
                Ob[base + 8]     = o[ni][2] + addend[base + 8];
                Ob[base + T + 8] = o[ni][3] + addend[base + T + 8];
            } else {
                Ob[base]         = o[ni][0];
                Ob[base + T]     = o[ni][1];
                Ob[base + 8]     = o[ni][2];
                Ob[base + T + 8] = o[ni][3];
            }
        }
    }
}

// ---------------------------------------------------------------------------
// LayerNorm: one warp per 512-wide row; emits split fp16 directly.
// ---------------------------------------------------------------------------
__global__ __launch_bounds__(256) void ln_kernel(
    const float* __restrict__ X, const float* __restrict__ gw,
    const float* __restrict__ gb, __half* __restrict__ Yh, __half* __restrict__ Yl)
{
    const int row  = blockIdx.x * 8 + (threadIdx.x >> 5);
    const int lane = threadIdx.x & 31;
    const float4* xr = (const float4*)(X + (size_t)row * D_);
    float4 v[4];
    float s = 0.f, ss = 0.f;
#pragma unroll
    for (int w = 0; w < 4; w++) {
        v[w] = xr[w*32 + lane];
        s  += v[w].x + v[w].y + v[w].z + v[w].w;
        ss += v[w].x*v[w].x + v[w].y*v[w].y + v[w].z*v[w].z + v[w].w*v[w].w;
    }
#pragma unroll
    for (int o = 16; o > 0; o >>= 1) {
        s  += __shfl_xor_sync(0xffffffffu, s, o);
        ss += __shfl_xor_sync(0xffffffffu, ss, o);
    }
    const float mean = s * (1.f/512.f);
    const float var  = ss * (1.f/512.f) - mean*mean;
    const float r = rsqrtf(var + 1e-5f);
    const float4* gr = (const float4*)gw;
    const float4* br = (const float4*)gb;
#pragma unroll
    for (int w = 0; w < 4; w++) {
        float4 gv = gr[w*32 + lane];
        float4 bv = br[w*32 + lane];
        float o0 = (v[w].x - mean) * r * gv.x + bv.x;
        float o1 = (v[w].y - mean) * r * gv.y + bv.y;
        float o2 = (v[w].z - mean) * r * gv.z + bv.z;
        float o3 = (v[w].w - mean) * r * gv.w + bv.w;
        __half h0,h1,h2,h3,l0,l1,l2,l3;
        split_h(o0,h0,l0); split_h(o1,h1,l1); split_h(o2,h2,l2); split_h(o3,h3,l3);
        size_t idx = (size_t)row * D_ + (w*32 + lane) * 4;
        *(uint2*)(Yh + idx) = make_uint2(pack2(h0,h1), pack2(h2,h3));
        *(uint2*)(Yl + idx) = make_uint2(pack2(l0,l1), pack2(l2,l3));
    }
}

// ---------------------------------------------------------------------------
// Combine: out = t1*sig(ld) + t2*(1-sig(ld)), ld = (t1-t2)@fw^T (bias cancels)
// ---------------------------------------------------------------------------
__global__ __launch_bounds__(256) void fuse2_kernel(
    const float4* __restrict__ t1, const float4* __restrict__ t2,
    const float4* __restrict__ ld, float4* __restrict__ out)
{
    int i = blockIdx.x * 256 + threadIdx.x;
    float4 x1 = t1[i], x2 = t2[i], d = ld[i];
    float a0 = 1.f / (1.f + __expf(-d.x));
    float a1 = 1.f / (1.f + __expf(-d.y));
    float a2 = 1.f / (1.f + __expf(-d.z));
    float a3 = 1.f / (1.f + __expf(-d.w));
    float4 o;
    o.x = x1.x * a0 + x2.x * (1.f - a0);
    o.y = x1.y * a1 + x2.y * (1.f - a1);
    o.z = x1.z * a2 + x2.z * (1.f - a2);
    o.w = x1.w * a3 + x2.w * (1.f - a3);
    out[i] = o;
}

// ---------------------------------------------------------------------------
extern "C" void kernel_launch(void* const* d_in, const int* in_sizes, int n_in,
                              void* d_out, int out_size)
{
    (void)in_sizes; (void)n_in; (void)out_size;
    const float* x    = (const float*)d_in[0];
    const float* qw   = (const float*)d_in[1];
    const float* qb   = (const float*)d_in[2];
    const float* kw   = (const float*)d_in[3];
    const float* kb   = (const float*)d_in[4];
    const float* vw   = (const float*)d_in[5];
    const float* vb   = (const float*)d_in[6];
    const float* temp = (const float*)d_in[7];
    const float* lng  = (const float*)d_in[8];
    const float* lnb  = (const float*)d_in[9];
    const float* fw   = (const float*)d_in[10];
    (void)d_in[11];   // fusion bias cancels in the softmax difference
    float* out = (float*)d_out;

    float *xr, *t1, *t2, *a1;
    __half *qh,*ql,*kh2,*kl2,*vh2,*vl2, *q2h,*q2l,*k2h,*k2l,*v2h,*v2l;
    __half *xh, *xl, *lnh, *lnl, *dh, *dl, *wh, *wl;
    cudaGetSymbolAddress((void**)&xr, g_xr);
    cudaGetSymbolAddress((void**)&t1, g_t1);
    cudaGetSymbolAddress((void**)&t2, g_t2);
    cudaGetSymbolAddress((void**)&a1, g_a1);
    cudaGetSymbolAddress((void**)&qh, g_qh);   cudaGetSymbolAddress((void**)&ql, g_ql);
    cudaGetSymbolAddress((void**)&kh2, g_kh);  cudaGetSymbolAddress((void**)&kl2, g_kl);
    cudaGetSymbolAddress((void**)&vh2, g_vh);  cudaGetSymbolAddress((void**)&vl2, g_vl);
    cudaGetSymbolAddress((void**)&q2h, g_q2h); cudaGetSymbolAddress((void**)&q2l, g_q2l);
    cudaGetSymbolAddress((void**)&k2h, g_k2h); cudaGetSymbolAddress((void**)&k2l, g_k2l);
    cudaGetSymbolAddress((void**)&v2h, g_v2h); cudaGetSymbolAddress((void**)&v2l, g_v2l);
    cudaGetSymbolAddress((void**)&xh, g_xh);   cudaGetSymbolAddress((void**)&xl, g_xl);
    cudaGetSymbolAddress((void**)&lnh, g_lnh); cudaGetSymbolAddress((void**)&lnl, g_lnl);
    cudaGetSymbolAddress((void**)&dh, g_dh);   cudaGetSymbolAddress((void**)&dl, g_dl);
    cudaGetSymbolAddress((void**)&wh, g_wh);   cudaGetSymbolAddress((void**)&wl, g_wl);

    const int gemmSmem = 3 * STAGE_B;                                   // 184320
    const int smem384 = (4*384*40 + 2*32*392) * 2 + 2*384*4 + (2*8*16*24) * 2;  // 188416
    const int smem128 = (4*128*40 + 2*32*136) * 2 + 2*128*4 + (2*8*16*24) * 2;
    cudaFuncSetAttribute(gemm_tc, cudaFuncAttributeMaxDynamicSharedMemorySize, gemmSmem);
    cudaFuncSetAttribute(attn_tc, cudaFuncAttributeMaxDynamicSharedMemorySize, smem384);

    // 1) pre-split x and all weight matrices
    SpArgs sp1;
    sp1.e[0] = { x,  xh,          xl,          BTD    };
    sp1.e[1] = { qw, wh + 0,      wl + 0,      5*WKN  };
    sp1.e[2] = { kw, wh + (size_t)5*WKN,  wl + (size_t)5*WKN,  5*WKN  };
    sp1.e[3] = { vw, wh + (size_t)10*WKN, wl + (size_t)10*WKN, 5*WKN  };
    sp1.e[4] = { fw, wh + (size_t)15*WKN, wl + (size_t)15*WKN, WKN    };
    split_kernel<<<dim3(512, 1, 5), 256>>>(sp1);

    // 2) QKV GEMMs (block0 full-T + blocks1-3 chunked), split epilogue
    G5Args ga1;
    ga1.s[0] = { xh, xl, 0,  0, qb, nullptr, qh,  ql,  0, 1 };
    ga1.s[1] = { xh, xl, 5,  0, kb, nullptr, kh2, kl2, 0, 1 };
    ga1.s[2] = { xh, xl, 10, 0, vb, nullptr, vh2, vl2, 0, 1 };
    ga1.s[3] = { xh, xl, 0,  0, qb, nullptr, q2h, q2l, 1, 1 };
    ga1.s[4] = { xh, xl, 5,  0, kb, nullptr, k2h, k2l, 1, 1 };
    ga1.s[5] = { xh, xl, 10, 0, vb, nullptr, v2h, v2l, 1, 1 };
    gemm_tc<<<dim3(2, 96, 6), 256, gemmSmem>>>(ga1);

    attn_tc<<<dim3(H_, 1, B_), 256, smem384>>>(qh, ql, kh2, kl2, vh2, vl2, temp, nullptr, xr, 384, 0);
    attn_tc<<<dim3(H_, 3, B_), 256, smem128>>>(q2h, q2l, k2h, k2l, v2h, v2l, temp, xr, t1, 128, 1);

    // 3) LayerNorm(t1) -> split fp16
    ln_kernel<<<M_/8, 256>>>(t1, lng, lnb, lnh, lnl);

    // 4) block4 QKV on LN output (reuse half buffers)
    G5Args ga2;
    ga2.s[0] = { lnh, lnl, 0,  4, qb, nullptr, qh,  ql,  0, 1 };
    ga2.s[1] = { lnh, lnl, 5,  4, kb, nullptr, kh2, kl2, 0, 1 };
    ga2.s[2] = { lnh, lnl, 10, 4, vb, nullptr, vh2, vl2, 0, 1 };
    ga2.s[3] = ga2.s[0]; ga2.s[4] = ga2.s[0]; ga2.s[5] = ga2.s[0];
    gemm_tc<<<dim3(2, 96, 3), 256, gemmSmem>>>(ga2);

    attn_tc<<<dim3(H_, 1, B_), 256, smem384>>>(qh, ql, kh2, kl2, vh2, vl2, temp, xr, t2, 384, 4);

    // 5) fusion: single GEMM on the difference (bias cancels in softmax)
    diff_split_kernel<<<BTD/4/256, 256>>>((const float4*)t1, (const float4*)t2, dh, dl);
    G5Args ga3;
    ga3.s[0] = { dh, dl, 15, 0, nullptr, a1, nullptr, nullptr, 0, 0 };
    ga3.s[1] = ga3.s[0]; ga3.s[2] = ga3.s[0]; ga3.s[3] = ga3.s[0];
    ga3.s[4] = ga3.s[0]; ga3.s[5] = ga3.s[0];
    gemm_tc<<<dim3(2, 96, 1), 256, gemmSmem>>>(ga3);

    fuse2_kernel<<<BTD/4/256, 256>>>((const float4*)t1, (const float4*)t2,
                                     (const float4*)a1, (float4*)out);
}

// round 9
// speedup vs baseline: 2.8297x; 1.0695x over previous
#include <cuda_runtime.h>
#include <cuda_fp16.h>
#include <math.h>
#include <stdint.h>

#define B_  32
#define T_  384
#define D_  512
#define H_  16
#define BTD (B_*T_*D_)     // 6291456
#define M_  (B_*T_)        // 12288
#define WKN (512*512)

// ---------------- scratch (static device globals; no cudaMalloc) ----------
__device__ float g_xr[BTD], g_t1[BTD], g_t2[BTD], g_a1[BTD];
__device__ __half g_qh[BTD], g_ql[BTD], g_kh[BTD], g_kl[BTD], g_vh[BTD], g_vl[BTD];
__device__ __half g_q2h[BTD], g_q2l[BTD], g_k2h[BTD], g_k2l[BTD], g_v2h[BTD], g_v2l[BTD];
__device__ __half g_xh[BTD],  g_xl[BTD];
__device__ __half g_lnh[BTD], g_lnl[BTD];
__device__ __half g_dh[BTD],  g_dl[BTD];
__device__ __half g_wh[16*WKN], g_wl[16*WKN];   // [qw0-4 | kw0-4 | vw0-4 | fw]

// ---------------- helpers --------------------------------------------------
__device__ __forceinline__ void split_h(float x, __half& hi, __half& lo) {
    hi = __float2half_rn(x);
    lo = __float2half_rn(x - __half2float(hi));
}
__device__ __forceinline__ unsigned pack2(__half a, __half b) {
    __half2 h = __halves2half2(a, b);
    return *reinterpret_cast<unsigned*>(&h);
}
__device__ __forceinline__ void mma_f16(float* c, const unsigned* a, unsigned b0, unsigned b1) {
    asm volatile("mma.sync.aligned.m16n8k16.row.col.f32.f16.f16.f32 "
        "{%0,%1,%2,%3}, {%4,%5,%6,%7}, {%8,%9}, {%0,%1,%2,%3};"
        : "+f"(c[0]), "+f"(c[1]), "+f"(c[2]), "+f"(c[3])
        : "r"(a[0]), "r"(a[1]), "r"(a[2]), "r"(a[3]), "r"(b0), "r"(b1));
}
__device__ __forceinline__ void ldsm4(unsigned* r, uint32_t addr) {
    asm volatile("ldmatrix.sync.aligned.m8n8.x4.shared.b16 {%0,%1,%2,%3}, [%4];"
        : "=r"(r[0]), "=r"(r[1]), "=r"(r[2]), "=r"(r[3]) : "r"(addr));
}
__device__ __forceinline__ uint32_t smem_u32(const void* p) {
    uint32_t a;
    asm("{ .reg .u64 t; cvta.to.shared.u64 t, %1; cvt.u32.u64 %0, t; }" : "=r"(a) : "l"(p));
    return a;
}
__device__ __forceinline__ void cpa16(uint32_t dst, const void* src) {
    asm volatile("cp.async.cg.shared.global [%0], [%1], 16;" :: "r"(dst), "l"(src) : "memory");
}

// ---------------------------------------------------------------------------
// fp16-split GEMM: CTA tile 128x256, 16 warps at 32x64 each (512 threads),
// k-chunk 32, 3-stage cp.async pipeline, ldmatrix operand loads.
// split=1: 3-mma hi/lo; split=0: single fp16 (hi inputs only; output split
// from the fp32 accumulator remains exact).
// ---------------------------------------------------------------------------
#define STAGE_B 61440u    // Ahi 10240 | Alo 10240 | Whi 20480 | Wlo 20480
struct G5 { const __half* Ah; const __half* Al; int wbase; int wadd;
            const float* bias; float* C; __half* Chi; __half* Clo;
            int chunk; int split; };
struct G5Args { G5 s[6]; };

__global__ __launch_bounds__(512) void gemm_tc(G5Args ga)
{
    extern __shared__ __half smh[];
    const uint32_t sm32 = smem_u32(smh);
    const int tid = threadIdx.x, lane = tid & 31, wid = tid >> 5;
    const int wm = wid & 3, wn = wid >> 2;            // 4 x 4 warps, 32x64 tile
    const int qr = lane >> 2, qc = lane & 3;
    const uint32_t ro = (lane & 7) + ((lane >> 3) & 1) * 8;
    const uint32_t co = (lane >> 4) * 8;

    const G5 sl = ga.s[blockIdx.z];
    const int m0 = blockIdx.y * 128, n0 = blockIdx.x * 256;
    const int widx = sl.chunk ? (1 + (m0 % 384) / 128) : sl.wadd;
    const __half* Wh = g_wh + (size_t)(sl.wbase + widx) * WKN;
    const __half* Wl = g_wl + (size_t)(sl.wbase + widx) * WKN;
    const float*  bp = sl.bias ? sl.bias + widx * 512 : nullptr;
    const int split = sl.split;

    auto issue = [&](int c) {
        const uint32_t base = sm32 + (uint32_t)(c % 3) * STAGE_B;
        const int kb = c * 32;
        {   // A: 128 rows, 1 round of 512 threads
            int row = tid >> 2, seg = tid & 3;
            uint32_t d = base + row * 80 + seg * 16;
            size_t gA = (size_t)(m0 + row) * 512 + kb + seg * 8;
            cpa16(d, sl.Ah + gA);
            if (split) cpa16(d + 10240, sl.Al + gA);
        }
#pragma unroll
        for (int r = 0; r < 2; r++) {                 // W: 256 rows, 2 rounds
            int e = tid + r * 512;
            int row = e >> 2, seg = e & 3;
            uint32_t d = base + 20480 + row * 80 + seg * 16;
            size_t gW = (size_t)(n0 + row) * 512 + kb + seg * 8;
            cpa16(d, Wh + gW);
            if (split) cpa16(d + 20480, Wl + gW);
        }
    };

    float acc[2][8][4];
#pragma unroll
    for (int mi = 0; mi < 2; mi++)
#pragma unroll
        for (int ni = 0; ni < 8; ni++)
#pragma unroll
            for (int j = 0; j < 4; j++) acc[mi][ni][j] = 0.f;

    issue(0);
    asm volatile("cp.async.commit_group;" ::: "memory");
    issue(1);
    asm volatile("cp.async.commit_group;" ::: "memory");

    for (int c = 0; c < 16; c++) {
        asm volatile("cp.async.wait_group 1;" ::: "memory");
        __syncthreads();
        const uint32_t sA = sm32 + (uint32_t)(c % 3) * STAGE_B;
        const uint32_t sW = sA + 20480;
#pragma unroll
        for (int ks = 0; ks < 2; ks++) {
            unsigned ah[2][4], al[2][4];
#pragma unroll
            for (int mi = 0; mi < 2; mi++) {
                uint32_t ra = sA + ((wm*32 + mi*16 + ro) * 40 + ks*16 + co) * 2;
                ldsm4(ah[mi], ra);
                if (split) ldsm4(al[mi], ra + 10240);
            }
#pragma unroll
            for (int p = 0; p < 4; p++) {
                uint32_t rw = sW + ((wn*64 + p*16 + ro) * 40 + ks*16 + co) * 2;
                unsigned wh4[4], wl4[4];
                ldsm4(wh4, rw);
                if (split) ldsm4(wl4, rw + 20480);
#pragma unroll
                for (int mi = 0; mi < 2; mi++) {
                    mma_f16(acc[mi][2*p],   ah[mi], wh4[0], wh4[2]);
                    mma_f16(acc[mi][2*p+1], ah[mi], wh4[1], wh4[3]);
                    if (split) {
                        mma_f16(acc[mi][2*p],   ah[mi], wl4[0], wl4[2]);
                        mma_f16(acc[mi][2*p],   al[mi], wh4[0], wh4[2]);
                        mma_f16(acc[mi][2*p+1], ah[mi], wl4[1], wl4[3]);
                        mma_f16(acc[mi][2*p+1], al[mi], wh4[1], wh4[3]);
                    }
                }
            }
        }
        if (c + 2 < 16) issue(c + 2);
        asm volatile("cp.async.commit_group;" ::: "memory");
    }

    // epilogue
#pragma unroll
    for (int mi = 0; mi < 2; mi++) {
#pragma unroll
        for (int ni = 0; ni < 8; ni++) {
            int row = m0 + wm * 32 + mi * 16 + qr;
            int col = n0 + wn * 64 + ni * 8 + 2 * qc;
            float bx = 0.f, by = 0.f;
            if (bp) { float2 bb = *(const float2*)(bp + col); bx = bb.x; by = bb.y; }
            float v00 = acc[mi][ni][0] + bx, v01 = acc[mi][ni][1] + by;
            float v10 = acc[mi][ni][2] + bx, v11 = acc[mi][ni][3] + by;
            if (sl.Chi) {
                __half h0,h1,l0,l1;
                split_h(v00,h0,l0); split_h(v01,h1,l1);
                *(unsigned*)(sl.Chi + (size_t)row*512 + col) = pack2(h0,h1);
                *(unsigned*)(sl.Clo + (size_t)row*512 + col) = pack2(l0,l1);
                split_h(v10,h0,l0); split_h(v11,h1,l1);
                *(unsigned*)(sl.Chi + (size_t)(row+8)*512 + col) = pack2(h0,h1);
                *(unsigned*)(sl.Clo + (size_t)(row+8)*512 + col) = pack2(l0,l1);
            } else {
                float2 o0 = { v00, v01 }, o1 = { v10, v11 };
                *(float2*)(sl.C + (size_t)row * 512 + col)       = o0;
                *(float2*)(sl.C + (size_t)(row + 8) * 512 + col) = o1;
            }
        }
    }
}

// ---------------------------------------------------------------------------
// split kernels: f32 -> (hi, lo) fp16 pairs
// ---------------------------------------------------------------------------
struct SpEnt { const float* src; __half* hi; __half* lo; int n; };
struct SpArgs { SpEnt e[5]; };

__global__ __launch_bounds__(256) void split_kernel(SpArgs sa)
{
    SpEnt E = sa.e[blockIdx.z];
    int stride = gridDim.x * 256;
    for (int i = blockIdx.x * 256 + threadIdx.x; i * 4 < E.n; i += stride) {
        float4 v = ((const float4*)E.src)[i];
        __half h0,h1,h2,h3,l0,l1,l2,l3;
        split_h(v.x,h0,l0); split_h(v.y,h1,l1); split_h(v.z,h2,l2); split_h(v.w,h3,l3);
        *(uint2*)(E.hi + 4*i) = make_uint2(pack2(h0,h1), pack2(h2,h3));
        *(uint2*)(E.lo + 4*i) = make_uint2(pack2(l0,l1), pack2(l2,l3));
    }
}

// diff+split: d = t1 - t2 -> (hi, lo)
__global__ __launch_bounds__(256) void diff_split_kernel(
    const float4* __restrict__ t1, const float4* __restrict__ t2,
    __half* __restrict__ hi, __half* __restrict__ lo)
{
    int i = blockIdx.x * 256 + threadIdx.x;
    float4 a = t1[i], b = t2[i];
    __half h0,h1,h2,h3,l0,l1,l2,l3;
    split_h(a.x-b.x,h0,l0); split_h(a.y-b.y,h1,l1);
    split_h(a.z-b.z,h2,l2); split_h(a.w-b.w,h3,l3);
    *(uint2*)(hi + 4*i) = make_uint2(pack2(h0,h1), pack2(h2,h3));
    *(uint2*)(lo + 4*i) = make_uint2(pack2(l0,l1), pack2(l2,l3));
}

// ---------------------------------------------------------------------------
// fp16-split attention with ldmatrix operand loads (unchanged).
// ---------------------------------------------------------------------------
__global__ __launch_bounds__(256) void attn_tc(
    const __half* __restrict__ Qbh, const __half* __restrict__ Qbl,
    const __half* __restrict__ Kbh, const __half* __restrict__ Kbl,
    const __half* __restrict__ Vbh, const __half* __restrict__ Vbl,
    const float* __restrict__ temp,
    const float* __restrict__ addend, float* __restrict__ Ob,
    int T, int tempBase)
{
    extern __shared__ __half smh[];
    const int QS = T + 8;
    __half* Khi = smh;                       // [T][40]
    __half* Klo = Khi + T * 40;
    __half* Vhi = Klo + T * 40;
    __half* Vlo = Vhi + T * 40;
    __half* Qhi = Vlo + T * 40;              // [32][QS]
    __half* Qlo = Qhi + 32 * QS;
    float*  Mv  = (float*)(Qlo + 32 * QS);
    float*  Lv  = Mv + T;
    __half* Pshi = (__half*)(Lv + T);        // 8 warps * [16][24]
    __half* Pslo = Pshi + 8 * 16 * 24;

    const uint32_t smA   = smem_u32(smh);
    const uint32_t KVoff = (uint32_t)T * 80;
    const uint32_t Qoff  = (uint32_t)32 * QS * 2;

    const int h = blockIdx.x, c = blockIdx.y, b = blockIdx.z;
    const int tid = threadIdx.x, lane = tid & 31, wid = tid >> 5;
    const int qr = lane >> 2, qc = lane & 3;
    const uint32_t ro = (lane & 7) + ((lane >> 3) & 1) * 8;
    const uint32_t co = (lane >> 4) * 8;
    const size_t off = (size_t)b * (T_*D_) + (size_t)c * (128*D_) + (size_t)h * 32 * T;
    const float scale = temp[(tempBase + c) * H_ + h];

    for (int idx = tid; idx < 32 * T; idx += 256) {
        int i = idx / T, t = idx - i * T;
        Khi[t*40 + i] = Kbh[off + idx];
        Klo[t*40 + i] = Kbl[off + idx];
        Vhi[t*40 + i] = Vbh[off + idx];
        Vlo[t*40 + i] = Vbl[off + idx];
        Qhi[i*QS + t] = Qbh[off + idx];
        Qlo[i*QS + t] = Qbl[off + idx];
    }
    __syncthreads();

    const int nb = T >> 4;
    const uint32_t KhiA = smA;
    const uint32_t VhiA = smA + 2 * KVoff;
    const uint32_t QhiA = smA + 4 * KVoff;

    // ---------------- Pass 1: row stats ----------------
    for (int tb = wid; tb < nb; tb += 8) {
        const int t0 = tb * 16;
        unsigned ah[2][4], al[2][4];
#pragma unroll
        for (int ks = 0; ks < 2; ks++) {
            uint32_t ra = KhiA + (((uint32_t)t0 + ro) * 40 + ks*16 + co) * 2;
            ldsm4(ah[ks], ra);
            ldsm4(al[ks], ra + KVoff);
        }
        float m0 = -3.0e38f, m1 = -3.0e38f, l0 = 0.f, l1 = 0.f;
        for (int s0 = 0; s0 < T; s0 += 64) {
            float cc[8][4];
#pragma unroll
            for (int nt = 0; nt < 8; nt++)
#pragma unroll
                for (int j = 0; j < 4; j++) cc[nt][j] = 0.f;
#pragma unroll
            for (int ks = 0; ks < 2; ks++) {
#pragma unroll
                for (int p = 0; p < 4; p++) {
                    uint32_t rv = VhiA + (((uint32_t)(s0 + p*16) + ro) * 40 + ks*16 + co) * 2;
                    unsigned vh4[4], vl4[4];
                    ldsm4(vh4, rv);
                    ldsm4(vl4, rv + KVoff);
                    mma_f16(cc[2*p],   ah[ks], vh4[0], vh4[2]);
                    mma_f16(cc[2*p],   ah[ks], vl4[0], vl4[2]);
                    mma_f16(cc[2*p],   al[ks], vh4[0], vh4[2]);
                    mma_f16(cc[2*p+1], ah[ks], vh4[1], vh4[3]);
                    mma_f16(cc[2*p+1], ah[ks], vl4[1], vl4[3]);
                    mma_f16(cc[2*p+1], al[ks], vh4[1], vh4[3]);
                }
            }
            float cm0 = -3.0e38f, cm1 = -3.0e38f;
#pragma unroll
            for (int nt = 0; nt < 8; nt++) {
#pragma unroll
                for (int j = 0; j < 4; j++) cc[nt][j] *= scale;
                cm0 = fmaxf(cm0, fmaxf(cc[nt][0], cc[nt][1]));
                cm1 = fmaxf(cm1, fmaxf(cc[nt][2], cc[nt][3]));
            }
            cm0 = fmaxf(cm0, __shfl_xor_sync(0xffffffffu, cm0, 1));
            cm0 = fmaxf(cm0, __shfl_xor_sync(0xffffffffu, cm0, 2));
            cm1 = fmaxf(cm1, __shfl_xor_sync(0xffffffffu, cm1, 1));
            cm1 = fmaxf(cm1, __shfl_xor_sync(0xffffffffu, cm1, 2));
            float M0 = fmaxf(m0, cm0), M1 = fmaxf(m1, cm1);
            float p0 = 0.f, p1 = 0.f;
#pragma unroll
            for (int nt = 0; nt < 8; nt++) {
                p0 += __expf(cc[nt][0] - M0) + __expf(cc[nt][1] - M0);
                p1 += __expf(cc[nt][2] - M1) + __expf(cc[nt][3] - M1);
            }
            p0 += __shfl_xor_sync(0xffffffffu, p0, 1);
            p0 += __shfl_xor_sync(0xffffffffu, p0, 2);
            p1 += __shfl_xor_sync(0xffffffffu, p1, 1);
            p1 += __shfl_xor_sync(0xffffffffu, p1, 2);
            l0 = l0 * __expf(m0 - M0) + p0;  m0 = M0;
            l1 = l1 * __expf(m1 - M1) + p1;  m1 = M1;
        }
        if (qc == 0) {
            Mv[t0 + qr]     = m0;  Lv[t0 + qr]     = 1.f / l0;
            Mv[t0 + qr + 8] = m1;  Lv[t0 + qr + 8] = 1.f / l1;
        }
    }
    __syncthreads();

    // ---------------- Pass 2: output ----------------
    __half* Pwh = Pshi + wid * (16 * 24);
    __half* Pwl = Pslo + wid * (16 * 24);
    const uint32_t PwhA = smem_u32(Pwh);
    const uint32_t PwlA = smem_u32(Pwl);
    for (int sb = wid; sb < nb; sb += 8) {
        const int s0 = sb * 16;
        unsigned vh[2][4], vl[2][4];
#pragma unroll
        for (int ks = 0; ks < 2; ks++) {
            uint32_t rv = VhiA + (((uint32_t)s0 + ro) * 40 + ks*16 + co) * 2;
            ldsm4(vh[ks], rv);
            ldsm4(vl[ks], rv + KVoff);
        }
        float o[4][4];
#pragma unroll
        for (int ni = 0; ni < 4; ni++)
#pragma unroll
            for (int j = 0; j < 4; j++) o[ni][j] = 0.f;

        for (int t0 = 0; t0 < T; t0 += 16) {
            float e[2][4];
#pragma unroll
            for (int nt = 0; nt < 2; nt++)
#pragma unroll
                for (int j = 0; j < 4; j++) e[nt][j] = 0.f;
#pragma unroll
            for (int ks = 0; ks < 2; ks++) {
                uint32_t rk = KhiA + (((uint32_t)t0 + ro) * 40 + ks*16 + co) * 2;
                unsigned kh4[4], kl4[4];
                ldsm4(kh4, rk);
                ldsm4(kl4, rk + KVoff);
                mma_f16(e[0], vh[ks], kh4[0], kh4[2]);
                mma_f16(e[0], vh[ks], kl4[0], kl4[2]);
                mma_f16(e[0], vl[ks], kh4[0], kh4[2]);
                mma_f16(e[1], vh[ks], kh4[1], kh4[3]);
                mma_f16(e[1], vh[ks], kl4[1], kl4[3]);
                mma_f16(e[1], vl[ks], kh4[1], kh4[3]);
            }
            __syncwarp();
#pragma unroll
            for (int nt = 0; nt < 2; nt++) {
                int tc = t0 + nt * 8 + 2 * qc;
                float mva = Mv[tc],   lva = Lv[tc];
                float mvb = Mv[tc+1], lvb = Lv[tc+1];
                float e0 = __expf(e[nt][0] * scale - mva) * lva;
                float e1 = __expf(e[nt][1] * scale - mvb) * lvb;
                float e2 = __expf(e[nt][2] * scale - mva) * lva;
                float e3 = __expf(e[nt][3] * scale - mvb) * lvb;
                __half h0, h1, h2, h3, g0, g1, g2, g3;
                split_h(e0, h0, g0); split_h(e1, h1, g1);
                split_h(e2, h2, g2); split_h(e3, h3, g3);
                *(unsigned*)(Pwh + qr*24     + nt*8 + 2*qc) = pack2(h0, h1);
                *(unsigned*)(Pwh + (qr+8)*24 + nt*8 + 2*qc) = pack2(h2, h3);
                *(unsigned*)(Pwl + qr*24     + nt*8 + 2*qc) = pack2(g0, g1);
                *(unsigned*)(Pwl + (qr+8)*24 + nt*8 + 2*qc) = pack2(g2, g3);
            }
            __syncwarp();
            unsigned ph[4], pl[4];
            ldsm4(ph, PwhA + (ro*24 + co) * 2);
            ldsm4(pl, PwlA + (ro*24 + co) * 2);
#pragma unroll
            for (int p2 = 0; p2 < 2; p2++) {
                uint32_t rq = QhiA + ((p2*16 + ro) * (uint32_t)QS + (uint32_t)t0 + co) * 2;
                unsigned q4[4], q4l[4];
                ldsm4(q4,  rq);
                ldsm4(q4l, rq + Qoff);
                mma_f16(o[2*p2],   ph, q4[0], q4[2]);
                mma_f16(o[2*p2],   ph, q4l[0], q4l[2]);
                mma_f16(o[2*p2],   pl, q4[0], q4[2]);
                mma_f16(o[2*p2+1], ph, q4[1], q4[3]);
                mma_f16(o[2*p2+1], ph, q4l[1], q4l[3]);
                mma_f16(o[2*p2+1], pl, q4[1], q4[3]);
            }
        }
#pragma unroll
        for (int ni = 0; ni < 4; ni++) {
            int icol = ni * 8 + 2 * qc;
            int srow = s0 + qr;
            size_t base = off + (size_t)icol * T + srow;
            if (addend != nullptr) {
                Ob[base]         = o[ni][0] + addend[base];
                Ob[base + T]     = o[ni][1] + addend[base + T];
                Ob[base + 8]     = o[ni][2] + addend[base + 8];
                Ob[base + T + 8] = o[ni][3] + addend[base + T + 8];
            } else {
                Ob[base]         = o[ni][0];
                Ob[base + T]     = o[ni][1];
                Ob[base + 8]     = o[ni][2];
                Ob[base + T + 8] = o[ni][3];
            }
        }
    }
}

// ---------------------------------------------------------------------------
// LayerNorm: one warp per 512-wide row; emits split fp16 directly.
// ---------------------------------------------------------------------------
__global__ __launch_bounds__(256) void ln_kernel(
    const float* __restrict__ X, const float* __restrict__ gw,
    const float* __restrict__ gb, __half* __restrict__ Yh, __half* __restrict__ Yl)
{
    const int row  = blockIdx.x * 8 + (threadIdx.x >> 5);
    const int lane = threadIdx.x & 31;
    const float4* xr = (const float4*)(X + (size_t)row * D_);
    float4 v[4];
    float s = 0.f, ss = 0.f;
#pragma unroll
    for (int w = 0; w < 4; w++) {
        v[w] = xr[w*32 + lane];
        s  += v[w].x + v[w].y + v[w].z + v[w].w;
        ss += v[w].x*v[w].x + v[w].y*v[w].y + v[w].z*v[w].z + v[w].w*v[w].w;
    }
#pragma unroll
    for (int o = 16; o > 0; o >>= 1) {
        s  += __shfl_xor_sync(0xffffffffu, s, o);
        ss += __shfl_xor_sync(0xffffffffu, ss, o);
    }
    const float mean = s * (1.f/512.f);
    const float var  = ss * (1.f/512.f) - mean*mean;
    const float r = rsqrtf(var + 1e-5f);
    const float4* gr = (const float4*)gw;
    const float4* br = (const float4*)gb;
#pragma unroll
    for (int w = 0; w < 4; w++) {
        float4 gv = gr[w*32 + lane];
        float4 bv = br[w*32 + lane];
        float o0 = (v[w].x - mean) * r * gv.x + bv.x;
        float o1 = (v[w].y - mean) * r * gv.y + bv.y;
        float o2 = (v[w].z - mean) * r * gv.z + bv.z;
        float o3 = (v[w].w - mean) * r * gv.w + bv.w;
        __half h0,h1,h2,h3,l0,l1,l2,l3;
        split_h(o0,h0,l0); split_h(o1,h1,l1); split_h(o2,h2,l2); split_h(o3,h3,l3);
        size_t idx = (size_t)row * D_ + (w*32 + lane) * 4;
        *(uint2*)(Yh + idx) = make_uint2(pack2(h0,h1), pack2(h2,h3));
        *(uint2*)(Yl + idx) = make_uint2(pack2(l0,l1), pack2(l2,l3));
    }
}

// ---------------------------------------------------------------------------
// Combine: out = t1*sig(ld) + t2*(1-sig(ld)), ld = (t1-t2)@fw^T (bias cancels)
// ---------------------------------------------------------------------------
__global__ __launch_bounds__(256) void fuse2_kernel(
    const float4* __restrict__ t1, const float4* __restrict__ t2,
    const float4* __restrict__ ld, float4* __restrict__ out)
{
    int i = blockIdx.x * 256 + threadIdx.x;
    float4 x1 = t1[i], x2 = t2[i], d = ld[i];
    float a0 = 1.f / (1.f + __expf(-d.x));
    float a1 = 1.f / (1.f + __expf(-d.y));
    float a2 = 1.f / (1.f + __expf(-d.z));
    float a3 = 1.f / (1.f + __expf(-d.w));
    float4 o;
    o.x = x1.x * a0 + x2.x * (1.f - a0);
    o.y = x1.y * a1 + x2.y * (1.f - a1);
    o.z = x1.z * a2 + x2.z * (1.f - a2);
    o.w = x1.w * a3 + x2.w * (1.f - a3);
    out[i] = o;
}

// ---------------------------------------------------------------------------
extern "C" void kernel_launch(void* const* d_in, const int* in_sizes, int n_in,
                              void* d_out, int out_size)
{
    (void)in_sizes; (void)n_in; (void)out_size;
    const float* x    = (const float*)d_in[0];
    const float* qw   = (const float*)d_in[1];
    const float* qb   = (const float*)d_in[2];
    const float* kw   = (const float*)d_in[3];
    const float* kb   = (const float*)d_in[4];
    const float* vw   = (const float*)d_in[5];
    const float* vb   = (const float*)d_in[6];
    const float* temp = (const float*)d_in[7];
    const float* lng  = (const float*)d_in[8];
    const float* lnb  = (const float*)d_in[9];
    const float* fw   = (const float*)d_in[10];
    (void)d_in[11];   // fusion bias cancels in the softmax difference
    float* out = (float*)d_out;

    float *xr, *t1, *t2, *a1;
    __half *qh,*ql,*kh2,*kl2,*vh2,*vl2, *q2h,*q2l,*k2h,*k2l,*v2h,*v2l;
    __half *xh, *xl, *lnh, *lnl, *dh, *dl, *wh, *wl;
    cudaGetSymbolAddress((void**)&xr, g_xr);
    cudaGetSymbolAddress((void**)&t1, g_t1);
    cudaGetSymbolAddress((void**)&t2, g_t2);
    cudaGetSymbolAddress((void**)&a1, g_a1);
    cudaGetSymbolAddress((void**)&qh, g_qh);   cudaGetSymbolAddress((void**)&ql, g_ql);
    cudaGetSymbolAddress((void**)&kh2, g_kh);  cudaGetSymbolAddress((void**)&kl2, g_kl);
    cudaGetSymbolAddress((void**)&vh2, g_vh);  cudaGetSymbolAddress((void**)&vl2, g_vl);
    cudaGetSymbolAddress((void**)&q2h, g_q2h); cudaGetSymbolAddress((void**)&q2l, g_q2l);
    cudaGetSymbolAddress((void**)&k2h, g_k2h); cudaGetSymbolAddress((void**)&k2l, g_k2l);
    cudaGetSymbolAddress((void**)&v2h, g_v2h); cudaGetSymbolAddress((void**)&v2l, g_v2l);
    cudaGetSymbolAddress((void**)&xh, g_xh);   cudaGetSymbolAddress((void**)&xl, g_xl);
    cudaGetSymbolAddress((void**)&lnh, g_lnh); cudaGetSymbolAddress((void**)&lnl, g_lnl);
    cudaGetSymbolAddress((void**)&dh, g_dh);   cudaGetSymbolAddress((void**)&dl, g_dl);
    cudaGetSymbolAddress((void**)&wh, g_wh);   cudaGetSymbolAddress((void**)&wl, g_wl);

    const int gemmSmem = 3 * STAGE_B;                                   // 184320
    const int smem384 = (4*384*40 + 2*32*392) * 2 + 2*384*4 + (2*8*16*24) * 2;  // 188416
    const int smem128 = (4*128*40 + 2*32*136) * 2 + 2*128*4 + (2*8*16*24) * 2;
    cudaFuncSetAttribute(gemm_tc, cudaFuncAttributeMaxDynamicSharedMemorySize, gemmSmem);
    cudaFuncSetAttribute(attn_tc, cudaFuncAttributeMaxDynamicSharedMemorySize, smem384);

    // 1) pre-split x and all weight matrices
    SpArgs sp1;
    sp1.e[0] = { x,  xh,          xl,          BTD    };
    sp1.e[1] = { qw, wh + 0,      wl + 0,      5*WKN  };
    sp1.e[2] = { kw, wh + (size_t)5*WKN,  wl + (size_t)5*WKN,  5*WKN  };
    sp1.e[3] = { vw, wh + (size_t)10*WKN, wl + (size_t)10*WKN, 5*WKN  };
    sp1.e[4] = { fw, wh + (size_t)15*WKN, wl + (size_t)15*WKN, WKN    };
    split_kernel<<<dim3(512, 1, 5), 256>>>(sp1);

    // 2) QKV GEMMs; Q projections single-fp16 (error enters output linearly)
    G5Args ga1;
    ga1.s[0] = { xh, xl, 0,  0, qb, nullptr, qh,  ql,  0, 0 };
    ga1.s[1] = { xh, xl, 5,  0, kb, nullptr, kh2, kl2, 0, 1 };
    ga1.s[2] = { xh, xl, 10, 0, vb, nullptr, vh2, vl2, 0, 1 };
    ga1.s[3] = { xh, xl, 0,  0, qb, nullptr, q2h, q2l, 1, 0 };
    ga1.s[4] = { xh, xl, 5,  0, kb, nullptr, k2h, k2l, 1, 1 };
    ga1.s[5] = { xh, xl, 10, 0, vb, nullptr, v2h, v2l, 1, 1 };
    gemm_tc<<<dim3(2, 96, 6), 512, gemmSmem>>>(ga1);

    attn_tc<<<dim3(H_, 1, B_), 256, smem384>>>(qh, ql, kh2, kl2, vh2, vl2, temp, nullptr, xr, 384, 0);
    attn_tc<<<dim3(H_, 3, B_), 256, smem128>>>(q2h, q2l, k2h, k2l, v2h, v2l, temp, xr, t1, 128, 1);

    // 3) LayerNorm(t1) -> split fp16
    ln_kernel<<<M_/8, 256>>>(t1, lng, lnb, lnh, lnl);

    // 4) block4 QKV on LN output (reuse half buffers)
    G5Args ga2;
    ga2.s[0] = { lnh, lnl, 0,  4, qb, nullptr, qh,  ql,  0, 0 };
    ga2.s[1] = { lnh, lnl, 5,  4, kb, nullptr, kh2, kl2, 0, 1 };
    ga2.s[2] = { lnh, lnl, 10, 4, vb, nullptr, vh2, vl2, 0, 1 };
    ga2.s[3] = ga2.s[0]; ga2.s[4] = ga2.s[0]; ga2.s[5] = ga2.s[0];
    gemm_tc<<<dim3(2, 96, 3), 512, gemmSmem>>>(ga2);

    attn_tc<<<dim3(H_, 1, B_), 256, smem384>>>(qh, ql, kh2, kl2, vh2, vl2, temp, xr, t2, 384, 4);

    // 5) fusion: single GEMM on the difference (bias cancels in softmax)
    diff_split_kernel<<<BTD/4/256, 256>>>((const float4*)t1, (const float4*)t2, dh, dl);
    G5Args ga3;
    ga3.s[0] = { dh, dl, 15, 0, nullptr, a1, nullptr, nullptr, 0, 0 };
    ga3.s[1] = ga3.s[0]; ga3.s[2] = ga3.s[0]; ga3.s[3] = ga3.s[0];
    ga3.s[4] = ga3.s[0]; ga3.s[5] = ga3.s[0];
    gemm_tc<<<dim3(2, 96, 1), 512, gemmSmem>>>(ga3);

    fuse2_kernel<<<BTD/4/256, 256>>>((const float4*)t1, (const float4*)t2,
                                     (const float4*)a1, (float4*)out);
}